// round 3
// baseline (speedup 1.0000x reference)
#include <cuda_runtime.h>
#include <math.h>
#include <stdint.h>

// ---------------- problem constants ----------------
#define N_ROWS   1024
#define E_DIM    512
#define QKV_DIM  1536
#define FF_DIM   2048
#define V_DIM    32000
#define N_BH     32
#define S_LEN    256

// ---------------- scratch ----------------
__device__ float g_x  [N_ROWS * E_DIM];
__device__ float g_h  [N_ROWS * E_DIM];
__device__ float g_qkv[N_ROWS * QKV_DIM];
__device__ float g_qk [N_BH * S_LEN * S_LEN];
__device__ float g_qr [N_BH * S_LEN * 512];
__device__ float g_o  [N_ROWS * E_DIM];
__device__ float g_g  [N_ROWS * FF_DIM];

// ---------------- reductions ----------------
__device__ __forceinline__ float warpSum(float v) {
    #pragma unroll
    for (int o = 16; o; o >>= 1) v += __shfl_xor_sync(0xffffffffu, v, o);
    return v;
}
__device__ __forceinline__ float warpMax(float v) {
    #pragma unroll
    for (int o = 16; o; o >>= 1) v = fmaxf(v, __shfl_xor_sync(0xffffffffu, v, o));
    return v;
}
__device__ __forceinline__ float blockSum(float v) {
    __shared__ float sm[8];
    int lane = threadIdx.x & 31, w = threadIdx.x >> 5;
    v = warpSum(v);
    __syncthreads();
    if (lane == 0) sm[w] = v;
    __syncthreads();
    float r = 0.f;
    #pragma unroll
    for (int i = 0; i < 8; i++) r += sm[i];
    return r;
}
__device__ __forceinline__ float blockMax(float v) {
    __shared__ float sm[8];
    int lane = threadIdx.x & 31, w = threadIdx.x >> 5;
    v = warpMax(v);
    __syncthreads();
    if (lane == 0) sm[w] = v;
    __syncthreads();
    float r = -3.4e38f;
    #pragma unroll
    for (int i = 0; i < 8; i++) r = fmaxf(r, sm[i]);
    return r;
}

// ---------------- embed + input layernorm ----------------
__global__ void embed_ln_k(const int* __restrict__ src, const float* __restrict__ emb,
                           const float* __restrict__ s, const float* __restrict__ b,
                           float* __restrict__ out) {
    int row = blockIdx.x, t = threadIdx.x;
    int tok = src[row];
    const float SC = 22.62741699796952f;
    float v0 = emb[(size_t)tok * E_DIM + t]       * SC;
    float v1 = emb[(size_t)tok * E_DIM + t + 256] * SC;
    float mean = blockSum(v0 + v1) * (1.f / E_DIM);
    float d0 = v0 - mean, d1 = v1 - mean;
    float var = blockSum(d0 * d0 + d1 * d1) * (1.f / E_DIM);
    float r = rsqrtf(var + 1e-5f);
    out[(size_t)row * E_DIM + t]       = d0 * r * s[t]       + b[t];
    out[(size_t)row * E_DIM + t + 256] = d1 * r * s[t + 256] + b[t + 256];
}

// ---------------- layernorm ----------------
__global__ void layernorm_k(const float* __restrict__ in, const float* __restrict__ s,
                            const float* __restrict__ b, float* __restrict__ out) {
    int row = blockIdx.x, t = threadIdx.x;
    float v0 = in[(size_t)row * E_DIM + t];
    float v1 = in[(size_t)row * E_DIM + t + 256];
    float mean = blockSum(v0 + v1) * (1.f / E_DIM);
    float d0 = v0 - mean, d1 = v1 - mean;
    float var = blockSum(d0 * d0 + d1 * d1) * (1.f / E_DIM);
    float r = rsqrtf(var + 1e-5f);
    out[(size_t)row * E_DIM + t]       = d0 * r * s[t]       + b[t];
    out[(size_t)row * E_DIM + t + 256] = d1 * r * s[t + 256] + b[t + 256];
}

// ---------------- softmax ----------------
__global__ void softmax_k(float* __restrict__ qk, const float* __restrict__ qr) {
    int bh = blockIdx.y, l = blockIdx.x, m = threadIdx.x;
    float* row = qk + (size_t)bh * (S_LEN * S_LEN) + (size_t)l * S_LEN;
    float bias = qr[(size_t)bh * (S_LEN * 512) + (size_t)l * 512 + (m - l + 255)];
    float v = row[m] * 0.125f + bias + ((m > l) ? 1.0f : 0.0f);
    float mx = blockMax(v);
    float e = expf(v - mx);
    float sum = blockSum(e);
    row[m] = e / sum;
}

// ---------------- tf32 helpers ----------------
__device__ __forceinline__ void split_tf32(float f, uint32_t& hi, uint32_t& lo) {
    asm("cvt.rna.tf32.f32 %0, %1;" : "=r"(hi) : "f"(f));
    float r = f - __uint_as_float(hi);
    asm("cvt.rna.tf32.f32 %0, %1;" : "=r"(lo) : "f"(r));
}

#define MMA_TF32(C, A0, A1, A2, A3, B0, B1)                                     \
    asm volatile("mma.sync.aligned.m16n8k8.row.col.f32.tf32.tf32.f32 "          \
                 "{%0,%1,%2,%3},{%4,%5,%6,%7},{%8,%9},{%0,%1,%2,%3};"           \
                 : "+f"(C[0]), "+f"(C[1]), "+f"(C[2]), "+f"(C[3])               \
                 : "r"(A0), "r"(A1), "r"(A2), "r"(A3), "r"(B0), "r"(B1))

// smem layout: hi/lo interleaved pairs, row stride 36 uint32 pairs-wise:
// element (m,k) at  m*36 + 2k  (hi at +0, lo at +1)
#define RS   36              // row stride in uint32
#define PLANE (128 * RS)     // one buffer of one operand
#define SMEM_BYTES (4 * PLANE * 4)   // As[2] + Bs[2], uint32

// ---------------- 3xTF32 GEMM, 128x128 tiles, pre-split smem ----------------
// BLAY 0: B is [N,K] (NT, C=A@B^T);  BLAY 1: B is [K,N] (NN)
// EPI: 0=bias, 1=residual add, 2=exact GELU.  NSPLIT>1 -> split-K atomicAdd (EPI==1 semantics)
// Requirements: M%128==0, (K/NSPLIT)%16==0.
template<int EPI, int BLAY, int NSPLIT>
__global__ __launch_bounds__(256)
void mma_gemm_k(const float* __restrict__ A, const float* __restrict__ B,
                const float* __restrict__ bias, float* __restrict__ C,
                int M, int N, int K, int lda, int ldb, int ldc,
                int aOffB, int aOffH, int bOffB, int bOffH, int cOffB, int cOffH) {
    extern __shared__ uint32_t smu[];
    uint32_t* As = smu;                 // [2][PLANE]
    uint32_t* Bs = smu + 2 * PLANE;     // [2][PLANE]

    int z = blockIdx.z;
    int sk = z % NSPLIT;
    int zz = z / NSPLIT;
    int zb = zz >> 3, zh = zz & 7;
    A += (size_t)zb * aOffB + (size_t)zh * aOffH;
    B += (size_t)zb * bOffB + (size_t)zh * bOffH;
    C += (size_t)zb * cOffB + (size_t)zh * cOffH;

    int kLen  = K / NSPLIT;
    int k0base = sk * kLen;
    int nk = kLen >> 4;

    int tid  = threadIdx.x;
    int lane = tid & 31, wid = tid >> 5;
    int wm0 = (wid >> 2) * 64;
    int wn0 = (wid & 3) * 32;
    int g   = lane >> 2;
    int tg  = lane & 3;
    int row0 = blockIdx.y * 128, col0 = blockIdx.x * 128;

    // loader indices
    int lrow = tid >> 1;            // 0..127
    int lks  = (tid & 1) * 8;       // 0 / 8
    int bk   = tid >> 4;            // 0..15  (NN)
    int bn   = (tid & 15) * 8;      // 0..120 (NN)

    float pa[8], pb[8];

    auto LOAD = [&](int chunk) {
        int kk = k0base + (chunk << 4);
        const float4* Ap = (const float4*)(A + (size_t)(row0 + lrow) * lda + kk + lks);
        float4 a0 = Ap[0], a1 = Ap[1];
        pa[0]=a0.x; pa[1]=a0.y; pa[2]=a0.z; pa[3]=a0.w;
        pa[4]=a1.x; pa[5]=a1.y; pa[6]=a1.z; pa[7]=a1.w;
        if (BLAY == 0) {
            float4 b0 = make_float4(0,0,0,0), b1 = b0;
            if (col0 + lrow < N) {
                const float4* Bp = (const float4*)(B + (size_t)(col0 + lrow) * ldb + kk + lks);
                b0 = Bp[0]; b1 = Bp[1];
            }
            pb[0]=b0.x; pb[1]=b0.y; pb[2]=b0.z; pb[3]=b0.w;
            pb[4]=b1.x; pb[5]=b1.y; pb[6]=b1.z; pb[7]=b1.w;
        } else {
            const float* Bp = B + (size_t)(kk + bk) * ldb + col0 + bn;
            float4 b0 = make_float4(0,0,0,0), b1 = b0;
            if (col0 + bn     < N) b0 = *(const float4*)(Bp);
            if (col0 + bn + 4 < N) b1 = *(const float4*)(Bp + 4);
            pb[0]=b0.x; pb[1]=b0.y; pb[2]=b0.z; pb[3]=b0.w;
            pb[4]=b1.x; pb[5]=b1.y; pb[6]=b1.z; pb[7]=b1.w;
        }
    };

    auto STORE = [&](int buf) {
        uint32_t* ad = As + buf * PLANE + lrow * RS + 2 * lks;
        #pragma unroll
        for (int j = 0; j < 8; j++) {
            uint32_t hi, lo; split_tf32(pa[j], hi, lo);
            *(uint2*)(ad + 2 * j) = make_uint2(hi, lo);
        }
        if (BLAY == 0) {
            uint32_t* bd = Bs + buf * PLANE + lrow * RS + 2 * lks;
            #pragma unroll
            for (int j = 0; j < 8; j++) {
                uint32_t hi, lo; split_tf32(pb[j], hi, lo);
                *(uint2*)(bd + 2 * j) = make_uint2(hi, lo);
            }
        } else {
            #pragma unroll
            for (int j = 0; j < 8; j++) {
                uint32_t hi, lo; split_tf32(pb[j], hi, lo);
                *(uint2*)(Bs + buf * PLANE + (bn + j) * RS + 2 * bk) = make_uint2(hi, lo);
            }
        }
    };

    float acc[4][4][4] = {};

    LOAD(0);
    STORE(0);
    __syncthreads();

    for (int i = 0; i < nk; i++) {
        int buf = i & 1;
        if (i + 1 < nk) LOAD(i + 1);

        const uint32_t* as = As + buf * PLANE;
        const uint32_t* bs = Bs + buf * PLANE;
        #pragma unroll
        for (int ks = 0; ks < 16; ks += 8) {
            uint32_t ahi[4][4], alo[4][4];
            #pragma unroll
            for (int mi = 0; mi < 4; mi++) {
                int m0 = wm0 + mi * 16 + g;
                uint2 u0 = *(const uint2*)(as + (m0)     * RS + 2 * (ks + tg));
                uint2 u1 = *(const uint2*)(as + (m0 + 8) * RS + 2 * (ks + tg));
                uint2 u2 = *(const uint2*)(as + (m0)     * RS + 2 * (ks + tg + 4));
                uint2 u3 = *(const uint2*)(as + (m0 + 8) * RS + 2 * (ks + tg + 4));
                ahi[mi][0]=u0.x; alo[mi][0]=u0.y;
                ahi[mi][1]=u1.x; alo[mi][1]=u1.y;
                ahi[mi][2]=u2.x; alo[mi][2]=u2.y;
                ahi[mi][3]=u3.x; alo[mi][3]=u3.y;
            }
            uint32_t bhi[4][2], blo[4][2];
            #pragma unroll
            for (int ni = 0; ni < 4; ni++) {
                int nb = wn0 + ni * 8 + g;
                uint2 v0 = *(const uint2*)(bs + nb * RS + 2 * (ks + tg));
                uint2 v1 = *(const uint2*)(bs + nb * RS + 2 * (ks + tg + 4));
                bhi[ni][0]=v0.x; blo[ni][0]=v0.y;
                bhi[ni][1]=v1.x; blo[ni][1]=v1.y;
            }
            #pragma unroll
            for (int mi = 0; mi < 4; mi++)
                #pragma unroll
                for (int ni = 0; ni < 4; ni++) {
                    MMA_TF32(acc[mi][ni], ahi[mi][0], ahi[mi][1], ahi[mi][2], ahi[mi][3],
                             bhi[ni][0], bhi[ni][1]);
                    MMA_TF32(acc[mi][ni], alo[mi][0], alo[mi][1], alo[mi][2], alo[mi][3],
                             bhi[ni][0], bhi[ni][1]);
                    MMA_TF32(acc[mi][ni], ahi[mi][0], ahi[mi][1], ahi[mi][2], ahi[mi][3],
                             blo[ni][0], blo[ni][1]);
                }
        }

        if (i + 1 < nk) STORE((i + 1) & 1);
        __syncthreads();
    }

    // ---- epilogue ----
    #pragma unroll
    for (int mi = 0; mi < 4; mi++) {
        #pragma unroll
        for (int rr = 0; rr < 2; rr++) {
            int r = row0 + wm0 + mi * 16 + g + rr * 8;
            float* Crow = C + (size_t)r * ldc;
            #pragma unroll
            for (int ni = 0; ni < 4; ni++) {
                int c = col0 + wn0 + ni * 8 + tg * 2;
                float v0 = acc[mi][ni][rr * 2];
                float v1 = acc[mi][ni][rr * 2 + 1];
                if (NSPLIT > 1) {
                    if (bias && sk == 0) {
                        if (c < N)     v0 += bias[c];
                        if (c + 1 < N) v1 += bias[c + 1];
                    }
                    if (c < N)     atomicAdd(&Crow[c], v0);
                    if (c + 1 < N) atomicAdd(&Crow[c + 1], v1);
                } else if (c + 1 < N) {
                    if (bias) { v0 += bias[c]; v1 += bias[c + 1]; }
                    if (EPI == 1) {
                        float2 old = *(const float2*)&Crow[c];
                        v0 += old.x; v1 += old.y;
                    }
                    if (EPI == 2) {
                        v0 = 0.5f * v0 * (1.f + erff(v0 * 0.7071067811865476f));
                        v1 = 0.5f * v1 * (1.f + erff(v1 * 0.7071067811865476f));
                    }
                    *(float2*)&Crow[c] = make_float2(v0, v1);
                } else if (c < N) {
                    if (bias) v0 += bias[c];
                    if (EPI == 1) v0 += Crow[c];
                    if (EPI == 2) v0 = 0.5f * v0 * (1.f + erff(v0 * 0.7071067811865476f));
                    Crow[c] = v0;
                }
            }
        }
    }
}

// ---------------- driver ----------------
extern "C" void kernel_launch(void* const* d_in, const int* in_sizes, int n_in,
                              void* d_out, int out_size) {
    const int*   src   = (const int*)  d_in[0];
    const float* emb   = (const float*)d_in[1];
    const float* rel   = (const float*)d_in[2];
    const float* nin_s = (const float*)d_in[3];
    const float* nin_b = (const float*)d_in[4];
    const float* inW   = (const float*)d_in[5];
    const float* inB   = (const float*)d_in[6];
    const float* outW  = (const float*)d_in[7];
    const float* outB  = (const float*)d_in[8];
    const float* ln1s  = (const float*)d_in[9];
    const float* ln1b  = (const float*)d_in[10];
    const float* ln2s  = (const float*)d_in[11];
    const float* ln2b  = (const float*)d_in[12];
    const float* w1    = (const float*)d_in[13];
    const float* b1    = (const float*)d_in[14];
    const float* w2    = (const float*)d_in[15];
    const float* b2    = (const float*)d_in[16];
    const float* nfs   = (const float*)d_in[17];
    const float* nfb   = (const float*)d_in[18];
    const float* decW  = (const float*)d_in[19];
    const float* decB  = (const float*)d_in[20];
    float* out = (float*)d_out;

    float *x, *h, *qkv, *qk, *qr, *o, *g;
    cudaGetSymbolAddress((void**)&x,   g_x);
    cudaGetSymbolAddress((void**)&h,   g_h);
    cudaGetSymbolAddress((void**)&qkv, g_qkv);
    cudaGetSymbolAddress((void**)&qk,  g_qk);
    cudaGetSymbolAddress((void**)&qr,  g_qr);
    cudaGetSymbolAddress((void**)&o,   g_o);
    cudaGetSymbolAddress((void**)&g,   g_g);

    cudaFuncSetAttribute(mma_gemm_k<0,0,1>, cudaFuncAttributeMaxDynamicSharedMemorySize, SMEM_BYTES);
    cudaFuncSetAttribute(mma_gemm_k<0,1,1>, cudaFuncAttributeMaxDynamicSharedMemorySize, SMEM_BYTES);
    cudaFuncSetAttribute(mma_gemm_k<1,0,4>, cudaFuncAttributeMaxDynamicSharedMemorySize, SMEM_BYTES);
    cudaFuncSetAttribute(mma_gemm_k<2,0,1>, cudaFuncAttributeMaxDynamicSharedMemorySize, SMEM_BYTES);

    embed_ln_k<<<N_ROWS, 256>>>(src, emb, nin_s, nin_b, x);

    for (int l = 0; l < 4; l++) {
        const float* inW_l  = inW  + (size_t)l * QKV_DIM * E_DIM;
        const float* inB_l  = inB  + (size_t)l * QKV_DIM;
        const float* outW_l = outW + (size_t)l * E_DIM * E_DIM;
        const float* outB_l = outB + (size_t)l * E_DIM;
        const float* w1_l   = w1   + (size_t)l * FF_DIM * E_DIM;
        const float* b1_l   = b1   + (size_t)l * FF_DIM;
        const float* w2_l   = w2   + (size_t)l * E_DIM * FF_DIM;
        const float* b2_l   = b2   + (size_t)l * E_DIM;

        layernorm_k<<<N_ROWS, 256>>>(x, ln1s + l * E_DIM, ln1b + l * E_DIM, h);

        // qkv = h @ inW^T + inB
        mma_gemm_k<0,0,1><<<dim3(12, 8, 1), 256, SMEM_BYTES>>>(h, inW_l, inB_l, qkv,
            N_ROWS, QKV_DIM, E_DIM, E_DIM, E_DIM, QKV_DIM, 0, 0, 0, 0, 0, 0);

        // scores = Q @ K^T (batched)
        mma_gemm_k<0,0,1><<<dim3(2, 2, N_BH), 256, SMEM_BYTES>>>(qkv, qkv + E_DIM, (const float*)0, qk,
            S_LEN, S_LEN, 64, QKV_DIM, QKV_DIM, S_LEN,
            S_LEN * QKV_DIM, 64,
            S_LEN * QKV_DIM, 64,
            8 * S_LEN * S_LEN, S_LEN * S_LEN);

        // qr = Q @ R^T
        mma_gemm_k<0,0,1><<<dim3(4, 2, N_BH), 256, SMEM_BYTES>>>(qkv, rel, (const float*)0, qr,
            S_LEN, 511, 64, QKV_DIM, E_DIM, 512,
            S_LEN * QKV_DIM, 64,
            0, 64,
            8 * S_LEN * 512, S_LEN * 512);

        softmax_k<<<dim3(S_LEN, N_BH), 256>>>(qk, qr);

        // o = probs @ V (NN)
        mma_gemm_k<0,1,1><<<dim3(1, 2, N_BH), 256, SMEM_BYTES>>>(qk, qkv + 2 * E_DIM, (const float*)0, o,
            S_LEN, 64, S_LEN, S_LEN, QKV_DIM, E_DIM,
            8 * S_LEN * S_LEN, S_LEN * S_LEN,
            S_LEN * QKV_DIM, 64,
            S_LEN * E_DIM, 64);

        // x += o @ outW^T + outB   (split-K 4, atomic)
        mma_gemm_k<1,0,4><<<dim3(4, 8, 4), 256, SMEM_BYTES>>>(o, outW_l, outB_l, x,
            N_ROWS, E_DIM, E_DIM, E_DIM, E_DIM, E_DIM, 0, 0, 0, 0, 0, 0);

        layernorm_k<<<N_ROWS, 256>>>(x, ln2s + l * E_DIM, ln2b + l * E_DIM, h);

        // g = gelu(h @ w1^T + b1)
        mma_gemm_k<2,0,1><<<dim3(16, 8, 1), 256, SMEM_BYTES>>>(h, w1_l, b1_l, g,
            N_ROWS, FF_DIM, E_DIM, E_DIM, E_DIM, FF_DIM, 0, 0, 0, 0, 0, 0);

        // x += g @ w2^T + b2   (split-K 4, atomic)
        mma_gemm_k<1,0,4><<<dim3(4, 8, 4), 256, SMEM_BYTES>>>(g, w2_l, b2_l, x,
            N_ROWS, E_DIM, FF_DIM, FF_DIM, FF_DIM, E_DIM, 0, 0, 0, 0, 0, 0);
    }

    layernorm_k<<<N_ROWS, 256>>>(x, nfs, nfb, h);

    // out = h @ dec_w^T + dec_b
    mma_gemm_k<0,0,1><<<dim3(250, 8, 1), 256, SMEM_BYTES>>>(h, decW, decB, out,
        N_ROWS, V_DIM, E_DIM, E_DIM, E_DIM, V_DIM, 0, 0, 0, 0, 0, 0);
}

// round 4
// speedup vs baseline: 1.9360x; 1.9360x over previous
#include <cuda_runtime.h>
#include <cuda_bf16.h>
#include <math.h>
#include <stdint.h>

// ---------------- problem constants ----------------
#define N_ROWS   1024
#define E_DIM    512
#define QKV_DIM  1536
#define FF_DIM   2048
#define V_DIM    32000
#define N_BH     32
#define S_LEN    256

// ---------------- f32 scratch ----------------
__device__ float g_x [N_ROWS * E_DIM];
__device__ float g_qk[N_BH * S_LEN * S_LEN];
__device__ float g_qr[N_BH * S_LEN * 512];

// ---------------- packed bf16 hi/lo planes (word = 2 consecutive-k bf16) ----------------
__device__ uint32_t p_h_hi  [N_ROWS * 256],  p_h_lo  [N_ROWS * 256];
__device__ uint32_t p_qkv_hi[N_ROWS * 768],  p_qkv_lo[N_ROWS * 768];
__device__ uint32_t p_pr_hi [N_BH * S_LEN * 128], p_pr_lo [N_BH * S_LEN * 128];
__device__ uint32_t p_o_hi  [N_ROWS * 256],  p_o_lo  [N_ROWS * 256];
__device__ uint32_t p_g_hi  [N_ROWS * 1024], p_g_lo  [N_ROWS * 1024];
__device__ uint32_t p_Wi_hi [4 * 1536 * 256], p_Wi_lo [4 * 1536 * 256];
__device__ uint32_t p_Wo_hi [4 * 512 * 256],  p_Wo_lo [4 * 512 * 256];
__device__ uint32_t p_W1_hi [4 * 2048 * 256], p_W1_lo [4 * 2048 * 256];
__device__ uint32_t p_W2_hi [4 * 512 * 1024], p_W2_lo [4 * 512 * 1024];
__device__ uint32_t p_Wd_hi [V_DIM * 256],    p_Wd_lo [V_DIM * 256];
__device__ uint32_t p_rel_hi[511 * 256],      p_rel_lo[511 * 256];

// ---------------- helpers ----------------
__device__ __forceinline__ void splitpack(float v0, float v1, uint32_t& hi, uint32_t& lo) {
    __nv_bfloat16 h0 = __float2bfloat16_rn(v0);
    __nv_bfloat16 h1 = __float2bfloat16_rn(v1);
    float r0 = v0 - __bfloat162float(h0);
    float r1 = v1 - __bfloat162float(h1);
    __nv_bfloat16 l0 = __float2bfloat16_rn(r0);
    __nv_bfloat16 l1 = __float2bfloat16_rn(r1);
    hi = (uint32_t)__bfloat16_as_ushort(h0) | ((uint32_t)__bfloat16_as_ushort(h1) << 16);
    lo = (uint32_t)__bfloat16_as_ushort(l0) | ((uint32_t)__bfloat16_as_ushort(l1) << 16);
}

__device__ __forceinline__ float warpSum(float v) {
    #pragma unroll
    for (int o = 16; o; o >>= 1) v += __shfl_xor_sync(0xffffffffu, v, o);
    return v;
}
__device__ __forceinline__ float warpMax(float v) {
    #pragma unroll
    for (int o = 16; o; o >>= 1) v = fmaxf(v, __shfl_xor_sync(0xffffffffu, v, o));
    return v;
}
__device__ __forceinline__ float blockSum(float v) {
    __shared__ float sm[8];
    int lane = threadIdx.x & 31, w = threadIdx.x >> 5;
    v = warpSum(v);
    __syncthreads();
    if (lane == 0) sm[w] = v;
    __syncthreads();
    float r = 0.f;
    #pragma unroll
    for (int i = 0; i < 8; i++) r += sm[i];
    return r;
}
__device__ __forceinline__ float blockMax(float v) {
    __shared__ float sm[8];
    int lane = threadIdx.x & 31, w = threadIdx.x >> 5;
    v = warpMax(v);
    __syncthreads();
    if (lane == 0) sm[w] = v;
    __syncthreads();
    float r = -3.4e38f;
    #pragma unroll
    for (int i = 0; i < 8; i++) r = fmaxf(r, sm[i]);
    return r;
}

// ---------------- elementwise f32 -> bf16 hi/lo plane split ----------------
__global__ void split_k(const float* __restrict__ in, uint32_t* __restrict__ hi,
                        uint32_t* __restrict__ lo, int nWords) {
    int i = blockIdx.x * 256 + threadIdx.x;
    if (i < nWords) {
        float2 v = *(const float2*)(in + 2 * (size_t)i);
        uint32_t h, l;
        splitpack(v.x, v.y, h, l);
        hi[i] = h; lo[i] = l;
    }
}

// ---------------- embed + input layernorm -> f32 x ----------------
__global__ void embed_ln_k(const int* __restrict__ src, const float* __restrict__ emb,
                           const float* __restrict__ s, const float* __restrict__ b,
                           float* __restrict__ out) {
    int row = blockIdx.x, t = threadIdx.x;
    int tok = src[row];
    const float SC = 22.62741699796952f;
    float v0 = emb[(size_t)tok * E_DIM + t]       * SC;
    float v1 = emb[(size_t)tok * E_DIM + t + 256] * SC;
    float mean = blockSum(v0 + v1) * (1.f / E_DIM);
    float d0 = v0 - mean, d1 = v1 - mean;
    float var = blockSum(d0 * d0 + d1 * d1) * (1.f / E_DIM);
    float r = rsqrtf(var + 1e-5f);
    out[(size_t)row * E_DIM + t]       = d0 * r * s[t]       + b[t];
    out[(size_t)row * E_DIM + t + 256] = d1 * r * s[t + 256] + b[t + 256];
}

// ---------------- layernorm f32 -> split planes ----------------
__global__ void layernorm_split_k(const float* __restrict__ in, const float* __restrict__ s,
                                  const float* __restrict__ b,
                                  uint32_t* __restrict__ oh, uint32_t* __restrict__ ol) {
    int row = blockIdx.x, t = threadIdx.x;
    float2 v = *(const float2*)(in + (size_t)row * E_DIM + 2 * t);
    float mean = blockSum(v.x + v.y) * (1.f / E_DIM);
    float d0 = v.x - mean, d1 = v.y - mean;
    float var = blockSum(d0 * d0 + d1 * d1) * (1.f / E_DIM);
    float r = rsqrtf(var + 1e-5f);
    float y0 = d0 * r * s[2 * t]     + b[2 * t];
    float y1 = d1 * r * s[2 * t + 1] + b[2 * t + 1];
    uint32_t h, l;
    splitpack(y0, y1, h, l);
    oh[(size_t)row * 256 + t] = h;
    ol[(size_t)row * 256 + t] = l;
}

// ---------------- softmax (scale + rel bias + mask) -> split probs planes ----------------
__global__ void softmax_split_k(const float* __restrict__ qk, const float* __restrict__ qr,
                                uint32_t* __restrict__ ph, uint32_t* __restrict__ pl) {
    int bh = blockIdx.y, l = blockIdx.x, m = threadIdx.x;
    const float* row = qk + (size_t)bh * (S_LEN * S_LEN) + (size_t)l * S_LEN;
    float bias = qr[(size_t)bh * (S_LEN * 512) + (size_t)l * 512 + (m - l + 255)];
    float v = row[m] * 0.125f + bias + ((m > l) ? 1.0f : 0.0f);
    float mx = blockMax(v);
    float e = expf(v - mx);
    float sum = blockSum(e);
    float p = e / sum;
    float pn = __shfl_xor_sync(0xffffffffu, p, 1);
    if ((m & 1) == 0) {
        uint32_t h, lo;
        splitpack(p, pn, h, lo);
        size_t idx = (size_t)bh * (S_LEN * 128) + (size_t)l * 128 + (m >> 1);
        ph[idx] = h; pl[idx] = lo;
    }
}

// ---------------- bf16 mma + cp.async ----------------
#define MMA_BF16(C, A0, A1, A2, A3, B0, B1)                                     \
    asm volatile("mma.sync.aligned.m16n8k16.row.col.f32.bf16.bf16.f32 "         \
                 "{%0,%1,%2,%3},{%4,%5,%6,%7},{%8,%9},{%0,%1,%2,%3};"           \
                 : "+f"(C[0]), "+f"(C[1]), "+f"(C[2]), "+f"(C[3])               \
                 : "r"(A0), "r"(A1), "r"(A2), "r"(A3), "r"(B0), "r"(B1))

__device__ __forceinline__ void cp16w(uint32_t* dst, const uint32_t* src, bool pred) {
    uint32_t d = (uint32_t)__cvta_generic_to_shared(dst);
    int sz = pred ? 16 : 0;
    asm volatile("cp.async.cg.shared.global [%0], [%1], 16, %2;"
                 :: "r"(d), "l"(src), "r"(sz));
}

// ---------------- bf16x3 GEMM, 128x128 CTA tile, chunk k=16 (8 words) ----------------
// Operands are packed bf16 hi/lo word planes [rows][Kw].
// BLAY 0: B plane is [N][Kw] (NT).  BLAY 1: B plane is [K][Nw] (NN, loader transpose).
// EPI: 0 = f32 out (+bias); 1 = f32 splitK atomicAdd (+bias at sk==0);
//      2 = planes out, bias + exact GELU; 3 = planes out (+bias).
// ldc: f32 elements for EPI 0/1, words for EPI 2/3.
template<int EPI, int BLAY, int NSPLIT>
__global__ __launch_bounds__(256, 2)
void bgemm(const uint32_t* __restrict__ Ah, const uint32_t* __restrict__ Al,
           const uint32_t* __restrict__ Bh, const uint32_t* __restrict__ Bl,
           const float* __restrict__ bias,
           float* __restrict__ Cf, uint32_t* __restrict__ Ch, uint32_t* __restrict__ Cl,
           int M, int N, int Kw, int ldaw, int ldbw, int ldc,
           int aOffB, int aOffH, int bOffB, int bOffH, int cOffB, int cOffH) {
    __shared__ uint32_t smem_[2][4][128 * 12];   // [buf][Ah,Al,Bh,Bl][row*12 + word]

    int z = blockIdx.z;
    int sk = z % NSPLIT;
    int zz = z / NSPLIT;
    int zb = zz >> 3, zh = zz & 7;
    Ah += (size_t)zb * aOffB + (size_t)zh * aOffH;
    Al += (size_t)zb * aOffB + (size_t)zh * aOffH;
    Bh += (size_t)zb * bOffB + (size_t)zh * bOffH;
    Bl += (size_t)zb * bOffB + (size_t)zh * bOffH;
    size_t cAdj = (size_t)zb * cOffB + (size_t)zh * cOffH;
    if (EPI <= 1) Cf += cAdj; else { Ch += cAdj; Cl += cAdj; }

    int kLenW = Kw / NSPLIT;
    int kw0   = sk * kLenW;
    int nk    = kLenW >> 3;

    int tid  = threadIdx.x;
    int lane = tid & 31, wid = tid >> 5;
    int wm0 = (wid >> 2) * 64;
    int wn0 = (wid & 3) * 32;
    int g   = lane >> 2;
    int tg  = lane & 3;
    int row0 = blockIdx.y * 128, col0 = blockIdx.x * 128;

    int lrow = tid >> 1;
    int seg  = (tid & 1) * 4;

    float acc[4][4][4] = {};

    auto COMPUTE = [&](int buf) {
        const uint32_t* ah = smem_[buf][0];
        const uint32_t* al = smem_[buf][1];
        const uint32_t* bh = smem_[buf][2];
        const uint32_t* bl = smem_[buf][3];
        uint32_t Bhf[4][2], Blf[4][2];
        #pragma unroll
        for (int ni = 0; ni < 4; ni++) {
            int nb = (wn0 + ni * 8 + g) * 12 + tg;
            Bhf[ni][0] = bh[nb]; Bhf[ni][1] = bh[nb + 4];
            Blf[ni][0] = bl[nb]; Blf[ni][1] = bl[nb + 4];
        }
        #pragma unroll
        for (int mi = 0; mi < 4; mi++) {
            int mb = (wm0 + mi * 16 + g) * 12 + tg;
            uint32_t Af[4] = { ah[mb], ah[mb + 8 * 12], ah[mb + 4], ah[mb + 8 * 12 + 4] };
            uint32_t Lf[4] = { al[mb], al[mb + 8 * 12], al[mb + 4], al[mb + 8 * 12 + 4] };
            #pragma unroll
            for (int ni = 0; ni < 4; ni++) {
                MMA_BF16(acc[mi][ni], Af[0], Af[1], Af[2], Af[3], Bhf[ni][0], Bhf[ni][1]);
                MMA_BF16(acc[mi][ni], Lf[0], Lf[1], Lf[2], Lf[3], Bhf[ni][0], Bhf[ni][1]);
                MMA_BF16(acc[mi][ni], Af[0], Af[1], Af[2], Af[3], Blf[ni][0], Blf[ni][1]);
            }
        }
    };

    if (BLAY == 0) {
        auto LOADNT = [&](int chunk, int buf) {
            int kws = kw0 + (chunk << 3) + seg;
            cp16w(&smem_[buf][0][lrow * 12 + seg], Ah + (size_t)(row0 + lrow) * ldaw + kws, true);
            cp16w(&smem_[buf][1][lrow * 12 + seg], Al + (size_t)(row0 + lrow) * ldaw + kws, true);
            bool p = (col0 + lrow) < N;
            cp16w(&smem_[buf][2][lrow * 12 + seg], Bh + (size_t)(col0 + lrow) * ldbw + kws, p);
            cp16w(&smem_[buf][3][lrow * 12 + seg], Bl + (size_t)(col0 + lrow) * ldbw + kws, p);
        };
        LOADNT(0, 0);
        asm volatile("cp.async.commit_group;");
        for (int i = 0; i < nk; i++) {
            int buf = i & 1;
            if (i + 1 < nk) LOADNT(i + 1, buf ^ 1);
            asm volatile("cp.async.commit_group;");
            asm volatile("cp.async.wait_group 1;");
            __syncthreads();
            COMPUTE(buf);
            __syncthreads();
        }
    } else {
        // NN: A planes [M][Kw] via cp.async; B planes [K][Nw] transposed by loader.
        int nw = tid >> 3;          // unit 0: 0..31 ; unit 1 adds 32
        int kw = tid & 7;
        for (int i = 0; i < nk; i++) {
            int kws = (i << 3);
            // load B regs (global, no smem)
            uint32_t w0h[2], w1h[2], w0l[2], w1l[2];
            #pragma unroll
            for (int u = 0; u < 2; u++) {
                int nwu = nw + u * 32;
                int k = (i << 4) + (kw << 1);
                bool valid = (2 * nwu + 1) < N;
                const uint32_t* sH = Bh + (size_t)k * ldbw + nwu;
                const uint32_t* sL = Bl + (size_t)k * ldbw + nwu;
                w0h[u] = valid ? sH[0] : 0u; w1h[u] = valid ? sH[ldbw] : 0u;
                w0l[u] = valid ? sL[0] : 0u; w1l[u] = valid ? sL[ldbw] : 0u;
            }
            __syncthreads();   // previous compute done
            cp16w(&smem_[0][0][lrow * 12 + seg], Ah + (size_t)(row0 + lrow) * ldaw + kws + seg, true);
            cp16w(&smem_[0][1][lrow * 12 + seg], Al + (size_t)(row0 + lrow) * ldaw + kws + seg, true);
            asm volatile("cp.async.commit_group;");
            #pragma unroll
            for (int u = 0; u < 2; u++) {
                int nwu = nw + u * 32;
                smem_[0][2][(2 * nwu)     * 12 + kw] = (w0h[u] & 0xFFFFu) | (w1h[u] << 16);
                smem_[0][2][(2 * nwu + 1) * 12 + kw] = (w0h[u] >> 16) | (w1h[u] & 0xFFFF0000u);
                smem_[0][3][(2 * nwu)     * 12 + kw] = (w0l[u] & 0xFFFFu) | (w1l[u] << 16);
                smem_[0][3][(2 * nwu + 1) * 12 + kw] = (w0l[u] >> 16) | (w1l[u] & 0xFFFF0000u);
            }
            asm volatile("cp.async.wait_group 0;");
            __syncthreads();
            COMPUTE(0);
        }
    }

    // ---------------- epilogue ----------------
    #pragma unroll
    for (int mi = 0; mi < 4; mi++) {
        #pragma unroll
        for (int rr = 0; rr < 2; rr++) {
            int r = row0 + wm0 + mi * 16 + g + rr * 8;
            #pragma unroll
            for (int ni = 0; ni < 4; ni++) {
                int c = col0 + wn0 + ni * 8 + tg * 2;
                float v0 = acc[mi][ni][rr * 2];
                float v1 = acc[mi][ni][rr * 2 + 1];
                if (EPI == 0) {
                    float* Crow = Cf + (size_t)r * ldc;
                    if (c + 1 < N) {
                        if (bias) { v0 += bias[c]; v1 += bias[c + 1]; }
                        *(float2*)&Crow[c] = make_float2(v0, v1);
                    } else if (c < N) {
                        if (bias) v0 += bias[c];
                        Crow[c] = v0;
                    }
                } else if (EPI == 1) {
                    float* Crow = Cf + (size_t)r * ldc;
                    if (bias && sk == 0) {
                        if (c < N)     v0 += bias[c];
                        if (c + 1 < N) v1 += bias[c + 1];
                    }
                    if (c < N)     atomicAdd(&Crow[c], v0);
                    if (c + 1 < N) atomicAdd(&Crow[c + 1], v1);
                } else {
                    if (c < N) {   // plane outputs always have even, fully-covered N
                        if (bias) { v0 += bias[c]; v1 += bias[c + 1]; }
                        if (EPI == 2) {
                            v0 = 0.5f * v0 * (1.f + erff(v0 * 0.7071067811865476f));
                            v1 = 0.5f * v1 * (1.f + erff(v1 * 0.7071067811865476f));
                        }
                        uint32_t h, l;
                        splitpack(v0, v1, h, l);
                        size_t idx = (size_t)r * ldc + (c >> 1);
                        Ch[idx] = h; Cl[idx] = l;
                    }
                }
            }
        }
    }
}

// ---------------- driver ----------------
extern "C" void kernel_launch(void* const* d_in, const int* in_sizes, int n_in,
                              void* d_out, int out_size) {
    const int*   src   = (const int*)  d_in[0];
    const float* emb   = (const float*)d_in[1];
    const float* rel   = (const float*)d_in[2];
    const float* nin_s = (const float*)d_in[3];
    const float* nin_b = (const float*)d_in[4];
    const float* inW   = (const float*)d_in[5];
    const float* inB   = (const float*)d_in[6];
    const float* outW  = (const float*)d_in[7];
    const float* outB  = (const float*)d_in[8];
    const float* ln1s  = (const float*)d_in[9];
    const float* ln1b  = (const float*)d_in[10];
    const float* ln2s  = (const float*)d_in[11];
    const float* ln2b  = (const float*)d_in[12];
    const float* w1    = (const float*)d_in[13];
    const float* b1    = (const float*)d_in[14];
    const float* w2    = (const float*)d_in[15];
    const float* b2    = (const float*)d_in[16];
    const float* nfs   = (const float*)d_in[17];
    const float* nfb   = (const float*)d_in[18];
    const float* decW  = (const float*)d_in[19];
    const float* decB  = (const float*)d_in[20];
    float* out = (float*)d_out;

    float *x, *qk, *qr;
    cudaGetSymbolAddress((void**)&x,  g_x);
    cudaGetSymbolAddress((void**)&qk, g_qk);
    cudaGetSymbolAddress((void**)&qr, g_qr);
    uint32_t *hH,*hL,*qkvH,*qkvL,*prH,*prL,*oH,*oL,*gH,*gL;
    uint32_t *WiH,*WiL,*WoH,*WoL,*W1H,*W1L,*W2H,*W2L,*WdH,*WdL,*relH,*relL;
    cudaGetSymbolAddress((void**)&hH,   p_h_hi);   cudaGetSymbolAddress((void**)&hL,   p_h_lo);
    cudaGetSymbolAddress((void**)&qkvH, p_qkv_hi); cudaGetSymbolAddress((void**)&qkvL, p_qkv_lo);
    cudaGetSymbolAddress((void**)&prH,  p_pr_hi);  cudaGetSymbolAddress((void**)&prL,  p_pr_lo);
    cudaGetSymbolAddress((void**)&oH,   p_o_hi);   cudaGetSymbolAddress((void**)&oL,   p_o_lo);
    cudaGetSymbolAddress((void**)&gH,   p_g_hi);   cudaGetSymbolAddress((void**)&gL,   p_g_lo);
    cudaGetSymbolAddress((void**)&WiH,  p_Wi_hi);  cudaGetSymbolAddress((void**)&WiL,  p_Wi_lo);
    cudaGetSymbolAddress((void**)&WoH,  p_Wo_hi);  cudaGetSymbolAddress((void**)&WoL,  p_Wo_lo);
    cudaGetSymbolAddress((void**)&W1H,  p_W1_hi);  cudaGetSymbolAddress((void**)&W1L,  p_W1_lo);
    cudaGetSymbolAddress((void**)&W2H,  p_W2_hi);  cudaGetSymbolAddress((void**)&W2L,  p_W2_lo);
    cudaGetSymbolAddress((void**)&WdH,  p_Wd_hi);  cudaGetSymbolAddress((void**)&WdL,  p_Wd_lo);
    cudaGetSymbolAddress((void**)&relH, p_rel_hi); cudaGetSymbolAddress((void**)&relL, p_rel_lo);

    // one-pass weight splits
    split_k<<<(4*1536*256 + 255)/256, 256>>>(inW,  WiH, WiL, 4*1536*256);
    split_k<<<(4*512*256  + 255)/256, 256>>>(outW, WoH, WoL, 4*512*256);
    split_k<<<(4*2048*256 + 255)/256, 256>>>(w1,   W1H, W1L, 4*2048*256);
    split_k<<<(4*512*1024 + 255)/256, 256>>>(w2,   W2H, W2L, 4*512*1024);
    split_k<<<(V_DIM*256  + 255)/256, 256>>>(decW, WdH, WdL, V_DIM*256);
    split_k<<<(511*256    + 255)/256, 256>>>(rel,  relH, relL, 511*256);

    embed_ln_k<<<N_ROWS, 256>>>(src, emb, nin_s, nin_b, x);

    for (int l = 0; l < 4; l++) {
        const uint32_t* WiHl = WiH + (size_t)l * 1536 * 256;
        const uint32_t* WiLl = WiL + (size_t)l * 1536 * 256;
        const uint32_t* WoHl = WoH + (size_t)l * 512 * 256;
        const uint32_t* WoLl = WoL + (size_t)l * 512 * 256;
        const uint32_t* W1Hl = W1H + (size_t)l * 2048 * 256;
        const uint32_t* W1Ll = W1L + (size_t)l * 2048 * 256;
        const uint32_t* W2Hl = W2H + (size_t)l * 512 * 1024;
        const uint32_t* W2Ll = W2L + (size_t)l * 512 * 1024;
        const float* inB_l  = inB  + (size_t)l * QKV_DIM;
        const float* outB_l = outB + (size_t)l * E_DIM;
        const float* b1_l   = b1   + (size_t)l * FF_DIM;
        const float* b2_l   = b2   + (size_t)l * E_DIM;

        layernorm_split_k<<<N_ROWS, 256>>>(x, ln1s + l*E_DIM, ln1b + l*E_DIM, hH, hL);

        // qkv planes = h @ inW^T + inB
        bgemm<3,0,1><<<dim3(12,8,1), 256>>>(hH, hL, WiHl, WiLl, inB_l,
            (float*)0, qkvH, qkvL, N_ROWS, QKV_DIM, 256, 256, 256, 768,
            0,0, 0,0, 0,0);

        // scores f32 = Q @ K^T  (per bh)
        bgemm<0,0,1><<<dim3(2,2,N_BH), 256>>>(qkvH, qkvL, qkvH + 256, qkvL + 256, (const float*)0,
            qk, (uint32_t*)0, (uint32_t*)0, S_LEN, S_LEN, 32, 768, 768, S_LEN,
            256*768, 32, 256*768, 32, 8*65536, 65536);

        // qr f32 = Q @ rel^T
        bgemm<0,0,1><<<dim3(4,2,N_BH), 256>>>(qkvH, qkvL, relH, relL, (const float*)0,
            qr, (uint32_t*)0, (uint32_t*)0, S_LEN, 511, 32, 768, 256, 512,
            256*768, 32, 0, 32, 8*131072, 131072);

        softmax_split_k<<<dim3(S_LEN, N_BH), 256>>>(qk, qr, prH, prL);

        // o planes = probs @ V  (NN)
        bgemm<3,1,1><<<dim3(1,2,N_BH), 256>>>(prH, prL, qkvH + 512, qkvL + 512, (const float*)0,
            (float*)0, oH, oL, S_LEN, 64, 128, 128, 768, 256,
            8*32768, 32768, 256*768, 32, 65536, 32);

        // x += o @ outW^T + outB   (splitK 4, atomic)
        bgemm<1,0,4><<<dim3(4,8,4), 256>>>(oH, oL, WoHl, WoLl, outB_l,
            x, (uint32_t*)0, (uint32_t*)0, N_ROWS, E_DIM, 256, 256, 256, E_DIM,
            0,0, 0,0, 0,0);

        layernorm_split_k<<<N_ROWS, 256>>>(x, ln2s + l*E_DIM, ln2b + l*E_DIM, hH, hL);

        // g planes = gelu(h @ w1^T + b1)
        bgemm<2,0,1><<<dim3(16,8,1), 256>>>(hH, hL, W1Hl, W1Ll, b1_l,
            (float*)0, gH, gL, N_ROWS, FF_DIM, 256, 256, 256, 1024,
            0,0, 0,0, 0,0);

        // x += g @ w2^T + b2   (splitK 4, atomic)
        bgemm<1,0,4><<<dim3(4,8,4), 256>>>(gH, gL, W2Hl, W2Ll, b2_l,
            x, (uint32_t*)0, (uint32_t*)0, N_ROWS, E_DIM, 1024, 1024, 1024, E_DIM,
            0,0, 0,0, 0,0);
    }

    layernorm_split_k<<<N_ROWS, 256>>>(x, nfs, nfb, hH, hL);

    // out f32 = h @ dec_w^T + dec_b
    bgemm<0,0,1><<<dim3(250,8,1), 256>>>(hH, hL, WdH, WdL, decB,
        out, (uint32_t*)0, (uint32_t*)0, N_ROWS, V_DIM, 256, 256, 256, V_DIM,
        0,0, 0,0, 0,0);
}

// round 5
// speedup vs baseline: 2.1951x; 1.1339x over previous
#include <cuda_runtime.h>
#include <cuda_bf16.h>
#include <math.h>
#include <stdint.h>

// ---------------- problem constants ----------------
#define N_ROWS   1024
#define E_DIM    512
#define QKV_DIM  1536
#define FF_DIM   2048
#define V_DIM    32000
#define N_BH     32
#define S_LEN    256

// ---------------- f32 scratch ----------------
__device__ float g_x [N_ROWS * E_DIM];
__device__ float g_qk[N_BH * S_LEN * S_LEN];
__device__ float g_qr[N_BH * S_LEN * 512];

// ---------------- packed bf16 hi/lo planes (word = 2 consecutive-k bf16) ----------------
__device__ uint32_t p_h_hi  [N_ROWS * 256],  p_h_lo  [N_ROWS * 256];
__device__ uint32_t p_qkv_hi[N_ROWS * 768],  p_qkv_lo[N_ROWS * 768];
__device__ uint32_t p_pr_hi [N_BH * S_LEN * 128], p_pr_lo [N_BH * S_LEN * 128];
__device__ uint32_t p_o_hi  [N_ROWS * 256],  p_o_lo  [N_ROWS * 256];
__device__ uint32_t p_g_hi  [N_ROWS * 1024], p_g_lo  [N_ROWS * 1024];
__device__ uint32_t p_Wi_hi [4 * 1536 * 256], p_Wi_lo [4 * 1536 * 256];
__device__ uint32_t p_Wo_hi [4 * 512 * 256],  p_Wo_lo [4 * 512 * 256];
__device__ uint32_t p_W1_hi [4 * 2048 * 256], p_W1_lo [4 * 2048 * 256];
__device__ uint32_t p_W2_hi [4 * 512 * 1024], p_W2_lo [4 * 512 * 1024];
__device__ uint32_t p_Wd_hi [V_DIM * 256],    p_Wd_lo [V_DIM * 256];
__device__ uint32_t p_rel_hi[511 * 256],      p_rel_lo[511 * 256];

// ---------------- helpers ----------------
__device__ __forceinline__ void splitpack(float v0, float v1, uint32_t& hi, uint32_t& lo) {
    __nv_bfloat16 h0 = __float2bfloat16_rn(v0);
    __nv_bfloat16 h1 = __float2bfloat16_rn(v1);
    float r0 = v0 - __bfloat162float(h0);
    float r1 = v1 - __bfloat162float(h1);
    __nv_bfloat16 l0 = __float2bfloat16_rn(r0);
    __nv_bfloat16 l1 = __float2bfloat16_rn(r1);
    hi = (uint32_t)__bfloat16_as_ushort(h0) | ((uint32_t)__bfloat16_as_ushort(h1) << 16);
    lo = (uint32_t)__bfloat16_as_ushort(l0) | ((uint32_t)__bfloat16_as_ushort(l1) << 16);
}

__device__ __forceinline__ float warpSum(float v) {
    #pragma unroll
    for (int o = 16; o; o >>= 1) v += __shfl_xor_sync(0xffffffffu, v, o);
    return v;
}
__device__ __forceinline__ float warpMax(float v) {
    #pragma unroll
    for (int o = 16; o; o >>= 1) v = fmaxf(v, __shfl_xor_sync(0xffffffffu, v, o));
    return v;
}
__device__ __forceinline__ float blockSum(float v) {
    __shared__ float sm[8];
    int lane = threadIdx.x & 31, w = threadIdx.x >> 5;
    v = warpSum(v);
    __syncthreads();
    if (lane == 0) sm[w] = v;
    __syncthreads();
    float r = 0.f;
    #pragma unroll
    for (int i = 0; i < 8; i++) r += sm[i];
    return r;
}
__device__ __forceinline__ float blockMax(float v) {
    __shared__ float sm[8];
    int lane = threadIdx.x & 31, w = threadIdx.x >> 5;
    v = warpMax(v);
    __syncthreads();
    if (lane == 0) sm[w] = v;
    __syncthreads();
    float r = -3.4e38f;
    #pragma unroll
    for (int i = 0; i < 8; i++) r = fmaxf(r, sm[i]);
    return r;
}

// ---------------- elementwise f32 -> bf16 hi/lo plane split (2 words/thread) ----------------
__global__ void split_k(const float* __restrict__ in, uint32_t* __restrict__ hi,
                        uint32_t* __restrict__ lo, int nWords) {
    int i = (blockIdx.x * 256 + threadIdx.x) * 2;
    if (i < nWords) {
        float4 v = *(const float4*)(in + 2 * (size_t)i);
        uint32_t h0, l0, h1, l1;
        splitpack(v.x, v.y, h0, l0);
        splitpack(v.z, v.w, h1, l1);
        *(uint2*)(hi + i) = make_uint2(h0, h1);
        *(uint2*)(lo + i) = make_uint2(l0, l1);
    }
}

// ---------------- embed + input layernorm -> f32 x ----------------
__global__ void embed_ln_k(const int* __restrict__ src, const float* __restrict__ emb,
                           const float* __restrict__ s, const float* __restrict__ b,
                           float* __restrict__ out) {
    int row = blockIdx.x, t = threadIdx.x;
    int tok = src[row];
    const float SC = 22.62741699796952f;
    float v0 = emb[(size_t)tok * E_DIM + t]       * SC;
    float v1 = emb[(size_t)tok * E_DIM + t + 256] * SC;
    float mean = blockSum(v0 + v1) * (1.f / E_DIM);
    float d0 = v0 - mean, d1 = v1 - mean;
    float var = blockSum(d0 * d0 + d1 * d1) * (1.f / E_DIM);
    float r = rsqrtf(var + 1e-5f);
    out[(size_t)row * E_DIM + t]       = d0 * r * s[t]       + b[t];
    out[(size_t)row * E_DIM + t + 256] = d1 * r * s[t + 256] + b[t + 256];
}

// ---------------- layernorm f32 -> split planes ----------------
__global__ void layernorm_split_k(const float* __restrict__ in, const float* __restrict__ s,
                                  const float* __restrict__ b,
                                  uint32_t* __restrict__ oh, uint32_t* __restrict__ ol) {
    int row = blockIdx.x, t = threadIdx.x;
    float2 v = *(const float2*)(in + (size_t)row * E_DIM + 2 * t);
    float mean = blockSum(v.x + v.y) * (1.f / E_DIM);
    float d0 = v.x - mean, d1 = v.y - mean;
    float var = blockSum(d0 * d0 + d1 * d1) * (1.f / E_DIM);
    float r = rsqrtf(var + 1e-5f);
    float y0 = d0 * r * s[2 * t]     + b[2 * t];
    float y1 = d1 * r * s[2 * t + 1] + b[2 * t + 1];
    uint32_t h, l;
    splitpack(y0, y1, h, l);
    oh[(size_t)row * 256 + t] = h;
    ol[(size_t)row * 256 + t] = l;
}

// ---------------- softmax (scale + rel bias + mask) -> split probs planes ----------------
__global__ void softmax_split_k(const float* __restrict__ qk, const float* __restrict__ qr,
                                uint32_t* __restrict__ ph, uint32_t* __restrict__ pl) {
    int bh = blockIdx.y, l = blockIdx.x, m = threadIdx.x;
    const float* row = qk + (size_t)bh * (S_LEN * S_LEN) + (size_t)l * S_LEN;
    float bias = qr[(size_t)bh * (S_LEN * 512) + (size_t)l * 512 + (m - l + 255)];
    float v = row[m] * 0.125f + bias + ((m > l) ? 1.0f : 0.0f);
    float mx = blockMax(v);
    float e = expf(v - mx);
    float sum = blockSum(e);
    float p = e / sum;
    float pn = __shfl_xor_sync(0xffffffffu, p, 1);
    if ((m & 1) == 0) {
        uint32_t h, lo;
        splitpack(p, pn, h, lo);
        size_t idx = (size_t)bh * (S_LEN * 128) + (size_t)l * 128 + (m >> 1);
        ph[idx] = h; pl[idx] = lo;
    }
}

// ---------------- mma / ldmatrix / cp.async primitives ----------------
#define MMA_BF16(C, A0, A1, A2, A3, B0, B1)                                     \
    asm volatile("mma.sync.aligned.m16n8k16.row.col.f32.bf16.bf16.f32 "         \
                 "{%0,%1,%2,%3},{%4,%5,%6,%7},{%8,%9},{%0,%1,%2,%3};"           \
                 : "+f"(C[0]), "+f"(C[1]), "+f"(C[2]), "+f"(C[3])               \
                 : "r"(A0), "r"(A1), "r"(A2), "r"(A3), "r"(B0), "r"(B1))

__device__ __forceinline__ void ldsm4(uint32_t& r0, uint32_t& r1, uint32_t& r2, uint32_t& r3,
                                      uint32_t addr) {
    asm volatile("ldmatrix.sync.aligned.m8n8.x4.shared.b16 {%0,%1,%2,%3}, [%4];"
                 : "=r"(r0), "=r"(r1), "=r"(r2), "=r"(r3) : "r"(addr));
}

__device__ __forceinline__ void cp16w(uint32_t* dst, const uint32_t* src, bool pred) {
    uint32_t d = (uint32_t)__cvta_generic_to_shared(dst);
    int sz = pred ? 16 : 0;
    asm volatile("cp.async.cg.shared.global [%0], [%1], 16, %2;"
                 :: "r"(d), "l"(src), "r"(sz));
}

// smem geometry (words / bytes)
#define PLANE_W   (128 * 12)            // one operand plane: 128 rows x 12-word stride
#define PLANE_B   (PLANE_W * 4)         // 6144 bytes
#define STAGE_W   (4 * PLANE_W)
#define STAGE_B   (4 * PLANE_B)         // 24576 bytes
#define STAGES    3
#define SMEM_BYTES (STAGES * STAGE_B)   // 73728 bytes

// ---------------- bf16x3 GEMM, 128x128 CTA tile, chunk k=16 (8 words) ----------------
// Operand planes: packed bf16 hi/lo words [rows][Kw].
// BLAY 0: B plane [N][Kw] (NT).  BLAY 1: B plane [K][Nw] (NN, loader transpose, 1 stage).
// EPI: 0 = f32 out (+bias); 1 = f32 splitK atomicAdd (+bias at sk==0);
//      2 = planes out, bias + exact GELU; 3 = planes out (+bias).
template<int EPI, int BLAY, int NSPLIT>
__global__ __launch_bounds__(256, 2)
void bgemm(const uint32_t* __restrict__ Ah, const uint32_t* __restrict__ Al,
           const uint32_t* __restrict__ Bh, const uint32_t* __restrict__ Bl,
           const float* __restrict__ bias,
           float* __restrict__ Cf, uint32_t* __restrict__ Ch, uint32_t* __restrict__ Cl,
           int M, int N, int Kw, int ldaw, int ldbw, int ldc,
           int aOffB, int aOffH, int bOffB, int bOffH, int cOffB, int cOffH) {
    extern __shared__ uint32_t smu[];   // [STAGES][4 planes][PLANE_W]

    int z = blockIdx.z;
    int sk = z % NSPLIT;
    int zz = z / NSPLIT;
    int zb = zz >> 3, zh = zz & 7;
    Ah += (size_t)zb * aOffB + (size_t)zh * aOffH;
    Al += (size_t)zb * aOffB + (size_t)zh * aOffH;
    Bh += (size_t)zb * bOffB + (size_t)zh * bOffH;
    Bl += (size_t)zb * bOffB + (size_t)zh * bOffH;
    size_t cAdj = (size_t)zb * cOffB + (size_t)zh * cOffH;
    if (EPI <= 1) Cf += cAdj; else { Ch += cAdj; Cl += cAdj; }

    int kLenW = Kw / NSPLIT;
    int kw0   = sk * kLenW;
    int nk    = kLenW >> 3;

    int tid  = threadIdx.x;
    int lane = tid & 31, wid = tid >> 5;
    int wm0 = (wid >> 2) * 64;
    int wn0 = (wid & 3) * 32;
    int g   = lane >> 2;
    int tg  = lane & 3;
    int row0 = blockIdx.y * 128, col0 = blockIdx.x * 128;

    int lrow = tid >> 1;
    int seg  = (tid & 1) * 4;

    uint32_t smBase = (uint32_t)__cvta_generic_to_shared(smu);
    // ldmatrix per-lane byte offsets within a stage
    uint32_t a_off = ((uint32_t)(wm0 + (lane & 15)) * 12 + ((lane & 16) ? 4 : 0)) * 4;
    uint32_t b_off = ((uint32_t)(wn0 + (lane & 7) + ((lane & 16) ? 8 : 0)) * 12
                      + ((lane & 8) ? 4 : 0)) * 4;

    float acc[4][4][4] = {};

    auto COMPUTE = [&](int buf) {
        uint32_t sb = smBase + (uint32_t)buf * STAGE_B;
        uint32_t aH = sb + a_off;
        uint32_t aL = aH + PLANE_B;
        uint32_t bH = sb + 2 * PLANE_B + b_off;
        uint32_t bL = bH + PLANE_B;
        uint32_t Bhf[4][2], Blf[4][2];
        ldsm4(Bhf[0][0], Bhf[0][1], Bhf[1][0], Bhf[1][1], bH);
        ldsm4(Bhf[2][0], Bhf[2][1], Bhf[3][0], Bhf[3][1], bH + 16 * 12 * 4);
        ldsm4(Blf[0][0], Blf[0][1], Blf[1][0], Blf[1][1], bL);
        ldsm4(Blf[2][0], Blf[2][1], Blf[3][0], Blf[3][1], bL + 16 * 12 * 4);
        #pragma unroll
        for (int mi = 0; mi < 4; mi++) {
            uint32_t Af[4], Lf[4];
            ldsm4(Af[0], Af[1], Af[2], Af[3], aH + (uint32_t)mi * 16 * 12 * 4);
            ldsm4(Lf[0], Lf[1], Lf[2], Lf[3], aL + (uint32_t)mi * 16 * 12 * 4);
            #pragma unroll
            for (int ni = 0; ni < 4; ni++) {
                MMA_BF16(acc[mi][ni], Af[0], Af[1], Af[2], Af[3], Bhf[ni][0], Bhf[ni][1]);
                MMA_BF16(acc[mi][ni], Lf[0], Lf[1], Lf[2], Lf[3], Bhf[ni][0], Bhf[ni][1]);
                MMA_BF16(acc[mi][ni], Af[0], Af[1], Af[2], Af[3], Blf[ni][0], Blf[ni][1]);
            }
        }
    };

    if (BLAY == 0) {
        auto LOADNT = [&](int chunk, int buf) {
            int kws = kw0 + (chunk << 3) + seg;
            uint32_t* st = smu + buf * STAGE_W;
            cp16w(st + lrow * 12 + seg,               Ah + (size_t)(row0 + lrow) * ldaw + kws, true);
            cp16w(st + PLANE_W + lrow * 12 + seg,     Al + (size_t)(row0 + lrow) * ldaw + kws, true);
            bool p = (col0 + lrow) < N;
            cp16w(st + 2 * PLANE_W + lrow * 12 + seg, Bh + (size_t)(col0 + lrow) * ldbw + kws, p);
            cp16w(st + 3 * PLANE_W + lrow * 12 + seg, Bl + (size_t)(col0 + lrow) * ldbw + kws, p);
        };
        int pre = (nk < STAGES - 1) ? nk : (STAGES - 1);
        for (int s = 0; s < pre; s++) {
            LOADNT(s, s);
            asm volatile("cp.async.commit_group;");
        }
        for (int i = 0; i < nk; i++) {
            int buf = i % STAGES;
            asm volatile("cp.async.wait_group %0;" :: "n"(STAGES - 2));
            __syncthreads();
            COMPUTE(buf);
            int nxt = i + STAGES - 1;
            if (nxt < nk) LOADNT(nxt, nxt % STAGES);
            asm volatile("cp.async.commit_group;");
        }
    } else {
        // NN: A planes [M][Kw] via cp.async; B planes [K][Nw] transposed by loader. 1 stage.
        int nw = tid >> 3;
        int kw = tid & 7;
        for (int i = 0; i < nk; i++) {
            int kws = (i << 3);
            uint32_t w0h[2], w1h[2], w0l[2], w1l[2];
            #pragma unroll
            for (int u = 0; u < 2; u++) {
                int nwu = nw + u * 32;
                int k = (i << 4) + (kw << 1);
                bool valid = (2 * nwu + 1) < N;
                const uint32_t* sH = Bh + (size_t)k * ldbw + nwu;
                const uint32_t* sL = Bl + (size_t)k * ldbw + nwu;
                w0h[u] = valid ? sH[0] : 0u; w1h[u] = valid ? sH[ldbw] : 0u;
                w0l[u] = valid ? sL[0] : 0u; w1l[u] = valid ? sL[ldbw] : 0u;
            }
            __syncthreads();
            cp16w(smu + lrow * 12 + seg,           Ah + (size_t)(row0 + lrow) * ldaw + kws + seg, true);
            cp16w(smu + PLANE_W + lrow * 12 + seg, Al + (size_t)(row0 + lrow) * ldaw + kws + seg, true);
            asm volatile("cp.async.commit_group;");
            #pragma unroll
            for (int u = 0; u < 2; u++) {
                int nwu = nw + u * 32;
                smu[2 * PLANE_W + (2 * nwu)     * 12 + kw] = (w0h[u] & 0xFFFFu) | (w1h[u] << 16);
                smu[2 * PLANE_W + (2 * nwu + 1) * 12 + kw] = (w0h[u] >> 16) | (w1h[u] & 0xFFFF0000u);
                smu[3 * PLANE_W + (2 * nwu)     * 12 + kw] = (w0l[u] & 0xFFFFu) | (w1l[u] << 16);
                smu[3 * PLANE_W + (2 * nwu + 1) * 12 + kw] = (w0l[u] >> 16) | (w1l[u] & 0xFFFF0000u);
            }
            asm volatile("cp.async.wait_group 0;");
            __syncthreads();
            COMPUTE(0);
        }
    }

    // ---------------- epilogue ----------------
    #pragma unroll
    for (int mi = 0; mi < 4; mi++) {
        #pragma unroll
        for (int rr = 0; rr < 2; rr++) {
            int r = row0 + wm0 + mi * 16 + g + rr * 8;
            #pragma unroll
            for (int ni = 0; ni < 4; ni++) {
                int c = col0 + wn0 + ni * 8 + tg * 2;
                float v0 = acc[mi][ni][rr * 2];
                float v1 = acc[mi][ni][rr * 2 + 1];
                if (EPI == 0) {
                    float* Crow = Cf + (size_t)r * ldc;
                    if (c + 1 < N) {
                        if (bias) { v0 += bias[c]; v1 += bias[c + 1]; }
                        *(float2*)&Crow[c] = make_float2(v0, v1);
                    } else if (c < N) {
                        if (bias) v0 += bias[c];
                        Crow[c] = v0;
                    }
                } else if (EPI == 1) {
                    float* Crow = Cf + (size_t)r * ldc;
                    if (bias && sk == 0) {
                        if (c < N)     v0 += bias[c];
                        if (c + 1 < N) v1 += bias[c + 1];
                    }
                    if (c < N)     atomicAdd(&Crow[c], v0);
                    if (c + 1 < N) atomicAdd(&Crow[c + 1], v1);
                } else {
                    if (c < N) {
                        if (bias) { v0 += bias[c]; v1 += bias[c + 1]; }
                        if (EPI == 2) {
                            v0 = 0.5f * v0 * (1.f + erff(v0 * 0.7071067811865476f));
                            v1 = 0.5f * v1 * (1.f + erff(v1 * 0.7071067811865476f));
                        }
                        uint32_t h, l;
                        splitpack(v0, v1, h, l);
                        size_t idx = (size_t)r * ldc + (c >> 1);
                        Ch[idx] = h; Cl[idx] = l;
                    }
                }
            }
        }
    }
}

// ---------------- driver ----------------
extern "C" void kernel_launch(void* const* d_in, const int* in_sizes, int n_in,
                              void* d_out, int out_size) {
    const int*   src   = (const int*)  d_in[0];
    const float* emb   = (const float*)d_in[1];
    const float* rel   = (const float*)d_in[2];
    const float* nin_s = (const float*)d_in[3];
    const float* nin_b = (const float*)d_in[4];
    const float* inW   = (const float*)d_in[5];
    const float* inB   = (const float*)d_in[6];
    const float* outW  = (const float*)d_in[7];
    const float* outB  = (const float*)d_in[8];
    const float* ln1s  = (const float*)d_in[9];
    const float* ln1b  = (const float*)d_in[10];
    const float* ln2s  = (const float*)d_in[11];
    const float* ln2b  = (const float*)d_in[12];
    const float* w1    = (const float*)d_in[13];
    const float* b1    = (const float*)d_in[14];
    const float* w2    = (const float*)d_in[15];
    const float* b2    = (const float*)d_in[16];
    const float* nfs   = (const float*)d_in[17];
    const float* nfb   = (const float*)d_in[18];
    const float* decW  = (const float*)d_in[19];
    const float* decB  = (const float*)d_in[20];
    float* out = (float*)d_out;

    float *x, *qk, *qr;
    cudaGetSymbolAddress((void**)&x,  g_x);
    cudaGetSymbolAddress((void**)&qk, g_qk);
    cudaGetSymbolAddress((void**)&qr, g_qr);
    uint32_t *hH,*hL,*qkvH,*qkvL,*prH,*prL,*oH,*oL,*gH,*gL;
    uint32_t *WiH,*WiL,*WoH,*WoL,*W1H,*W1L,*W2H,*W2L,*WdH,*WdL,*relH,*relL;
    cudaGetSymbolAddress((void**)&hH,   p_h_hi);   cudaGetSymbolAddress((void**)&hL,   p_h_lo);
    cudaGetSymbolAddress((void**)&qkvH, p_qkv_hi); cudaGetSymbolAddress((void**)&qkvL, p_qkv_lo);
    cudaGetSymbolAddress((void**)&prH,  p_pr_hi);  cudaGetSymbolAddress((void**)&prL,  p_pr_lo);
    cudaGetSymbolAddress((void**)&oH,   p_o_hi);   cudaGetSymbolAddress((void**)&oL,   p_o_lo);
    cudaGetSymbolAddress((void**)&gH,   p_g_hi);   cudaGetSymbolAddress((void**)&gL,   p_g_lo);
    cudaGetSymbolAddress((void**)&WiH,  p_Wi_hi);  cudaGetSymbolAddress((void**)&WiL,  p_Wi_lo);
    cudaGetSymbolAddress((void**)&WoH,  p_Wo_hi);  cudaGetSymbolAddress((void**)&WoL,  p_Wo_lo);
    cudaGetSymbolAddress((void**)&W1H,  p_W1_hi);  cudaGetSymbolAddress((void**)&W1L,  p_W1_lo);
    cudaGetSymbolAddress((void**)&W2H,  p_W2_hi);  cudaGetSymbolAddress((void**)&W2L,  p_W2_lo);
    cudaGetSymbolAddress((void**)&WdH,  p_Wd_hi);  cudaGetSymbolAddress((void**)&WdL,  p_Wd_lo);
    cudaGetSymbolAddress((void**)&relH, p_rel_hi); cudaGetSymbolAddress((void**)&relL, p_rel_lo);

    cudaFuncSetAttribute(bgemm<3,0,1>, cudaFuncAttributeMaxDynamicSharedMemorySize, SMEM_BYTES);
    cudaFuncSetAttribute(bgemm<0,0,1>, cudaFuncAttributeMaxDynamicSharedMemorySize, SMEM_BYTES);
    cudaFuncSetAttribute(bgemm<3,1,1>, cudaFuncAttributeMaxDynamicSharedMemorySize, SMEM_BYTES);
    cudaFuncSetAttribute(bgemm<1,0,4>, cudaFuncAttributeMaxDynamicSharedMemorySize, SMEM_BYTES);
    cudaFuncSetAttribute(bgemm<2,0,1>, cudaFuncAttributeMaxDynamicSharedMemorySize, SMEM_BYTES);

    // one-pass weight splits (2 words per thread)
    split_k<<<(4*1536*256/2 + 255)/256, 256>>>(inW,  WiH, WiL, 4*1536*256);
    split_k<<<(4*512*256/2  + 255)/256, 256>>>(outW, WoH, WoL, 4*512*256);
    split_k<<<(4*2048*256/2 + 255)/256, 256>>>(w1,   W1H, W1L, 4*2048*256);
    split_k<<<(4*512*1024/2 + 255)/256, 256>>>(w2,   W2H, W2L, 4*512*1024);
    split_k<<<(V_DIM*256/2  + 255)/256, 256>>>(decW, WdH, WdL, V_DIM*256);
    split_k<<<(511*256/2    + 255)/256, 256>>>(rel,  relH, relL, 511*256);

    embed_ln_k<<<N_ROWS, 256>>>(src, emb, nin_s, nin_b, x);

    for (int l = 0; l < 4; l++) {
        const uint32_t* WiHl = WiH + (size_t)l * 1536 * 256;
        const uint32_t* WiLl = WiL + (size_t)l * 1536 * 256;
        const uint32_t* WoHl = WoH + (size_t)l * 512 * 256;
        const uint32_t* WoLl = WoL + (size_t)l * 512 * 256;
        const uint32_t* W1Hl = W1H + (size_t)l * 2048 * 256;
        const uint32_t* W1Ll = W1L + (size_t)l * 2048 * 256;
        const uint32_t* W2Hl = W2H + (size_t)l * 512 * 1024;
        const uint32_t* W2Ll = W2L + (size_t)l * 512 * 1024;
        const float* inB_l  = inB  + (size_t)l * QKV_DIM;
        const float* outB_l = outB + (size_t)l * E_DIM;
        const float* b1_l   = b1   + (size_t)l * FF_DIM;
        const float* b2_l   = b2   + (size_t)l * E_DIM;

        layernorm_split_k<<<N_ROWS, 256>>>(x, ln1s + l*E_DIM, ln1b + l*E_DIM, hH, hL);

        // qkv planes = h @ inW^T + inB
        bgemm<3,0,1><<<dim3(12,8,1), 256, SMEM_BYTES>>>(hH, hL, WiHl, WiLl, inB_l,
            (float*)0, qkvH, qkvL, N_ROWS, QKV_DIM, 256, 256, 256, 768,
            0,0, 0,0, 0,0);

        // scores f32 = Q @ K^T  (per bh)
        bgemm<0,0,1><<<dim3(2,2,N_BH), 256, SMEM_BYTES>>>(qkvH, qkvL, qkvH + 256, qkvL + 256, (const float*)0,
            qk, (uint32_t*)0, (uint32_t*)0, S_LEN, S_LEN, 32, 768, 768, S_LEN,
            256*768, 32, 256*768, 32, 8*65536, 65536);

        // qr f32 = Q @ rel^T
        bgemm<0,0,1><<<dim3(4,2,N_BH), 256, SMEM_BYTES>>>(qkvH, qkvL, relH, relL, (const float*)0,
            qr, (uint32_t*)0, (uint32_t*)0, S_LEN, 511, 32, 768, 256, 512,
            256*768, 32, 0, 32, 8*131072, 131072);

        softmax_split_k<<<dim3(S_LEN, N_BH), 256>>>(qk, qr, prH, prL);

        // o planes = probs @ V  (NN)
        bgemm<3,1,1><<<dim3(1,2,N_BH), 256, SMEM_BYTES>>>(prH, prL, qkvH + 512, qkvL + 512, (const float*)0,
            (float*)0, oH, oL, S_LEN, 64, 128, 128, 768, 256,
            8*32768, 32768, 256*768, 32, 65536, 32);

        // x += o @ outW^T + outB   (splitK 4, atomic)
        bgemm<1,0,4><<<dim3(4,8,4), 256, SMEM_BYTES>>>(oH, oL, WoHl, WoLl, outB_l,
            x, (uint32_t*)0, (uint32_t*)0, N_ROWS, E_DIM, 256, 256, 256, E_DIM,
            0,0, 0,0, 0,0);

        layernorm_split_k<<<N_ROWS, 256>>>(x, ln2s + l*E_DIM, ln2b + l*E_DIM, hH, hL);

        // g planes = gelu(h @ w1^T + b1)
        bgemm<2,0,1><<<dim3(16,8,1), 256, SMEM_BYTES>>>(hH, hL, W1Hl, W1Ll, b1_l,
            (float*)0, gH, gL, N_ROWS, FF_DIM, 256, 256, 256, 1024,
            0,0, 0,0, 0,0);

        // x += g @ w2^T + b2   (splitK 4, atomic)
        bgemm<1,0,4><<<dim3(4,8,4), 256, SMEM_BYTES>>>(gH, gL, W2Hl, W2Ll, b2_l,
            x, (uint32_t*)0, (uint32_t*)0, N_ROWS, E_DIM, 1024, 1024, 1024, E_DIM,
            0,0, 0,0, 0,0);
    }

    layernorm_split_k<<<N_ROWS, 256>>>(x, nfs, nfb, hH, hL);

    // out f32 = h @ dec_w^T + dec_b
    bgemm<0,0,1><<<dim3(250,8,1), 256, SMEM_BYTES>>>(hH, hL, WdH, WdL, decB,
        out, (uint32_t*)0, (uint32_t*)0, N_ROWS, V_DIM, 256, 256, 256, V_DIM,
        0,0, 0,0, 0,0);
}

// round 7
// speedup vs baseline: 2.7579x; 1.2564x over previous
#include <cuda_runtime.h>
#include <cuda_fp16.h>
#include <math.h>
#include <stdint.h>

// ---------------- problem constants ----------------
#define N_ROWS   1024
#define E_DIM    512
#define QKV_DIM  1536
#define FF_DIM   2048
#define V_DIM    32000
#define N_BH     32
#define S_LEN    256

// ---------------- f32 scratch ----------------
__device__ float g_x [N_ROWS * E_DIM];
__device__ float g_qk[N_BH * S_LEN * S_LEN];
__device__ float g_qr[N_BH * S_LEN * 512];

// ---------------- packed fp16 hi/lo planes (word = 2 consecutive-k halves) ----------------
__device__ uint32_t p_h_hi  [N_ROWS * 256],  p_h_lo  [N_ROWS * 256];
__device__ uint32_t p_qkv_hi[N_ROWS * 768],  p_qkv_lo[N_ROWS * 768];
__device__ uint32_t p_pr_hi [N_BH * S_LEN * 128], p_pr_lo [N_BH * S_LEN * 128];
__device__ uint32_t p_o_hi  [N_ROWS * 256],  p_o_lo  [N_ROWS * 256];
__device__ uint32_t p_g_hi  [N_ROWS * 1024], p_g_lo  [N_ROWS * 1024];
__device__ uint32_t p_Wi_hi [4 * 1536 * 256];
__device__ uint32_t p_Wo_hi [4 * 512 * 256];
__device__ uint32_t p_W1_hi [4 * 2048 * 256];
__device__ uint32_t p_W2_hi [4 * 512 * 1024];
__device__ uint32_t p_Wd_hi [V_DIM * 256];
__device__ uint32_t p_rel_hi[511 * 256];

// ---------------- helpers ----------------
__device__ __forceinline__ void splitpack(float v0, float v1, uint32_t& hi, uint32_t& lo) {
    __half h0 = __float2half_rn(v0);
    __half h1 = __float2half_rn(v1);
    float r0 = v0 - __half2float(h0);
    float r1 = v1 - __half2float(h1);
    __half l0 = __float2half_rn(r0);
    __half l1 = __float2half_rn(r1);
    hi = (uint32_t)__half_as_ushort(h0) | ((uint32_t)__half_as_ushort(h1) << 16);
    lo = (uint32_t)__half_as_ushort(l0) | ((uint32_t)__half_as_ushort(l1) << 16);
}
__device__ __forceinline__ uint32_t pack_hi(float v0, float v1) {
    __half h0 = __float2half_rn(v0);
    __half h1 = __float2half_rn(v1);
    return (uint32_t)__half_as_ushort(h0) | ((uint32_t)__half_as_ushort(h1) << 16);
}

__device__ __forceinline__ float warpSum(float v) {
    #pragma unroll
    for (int o = 16; o; o >>= 1) v += __shfl_xor_sync(0xffffffffu, v, o);
    return v;
}
__device__ __forceinline__ float warpMax(float v) {
    #pragma unroll
    for (int o = 16; o; o >>= 1) v = fmaxf(v, __shfl_xor_sync(0xffffffffu, v, o));
    return v;
}
__device__ __forceinline__ float blockSum(float v) {
    __shared__ float sm[8];
    int lane = threadIdx.x & 31, w = threadIdx.x >> 5;
    v = warpSum(v);
    __syncthreads();
    if (lane == 0) sm[w] = v;
    __syncthreads();
    float r = 0.f;
    #pragma unroll
    for (int i = 0; i < 8; i++) r += sm[i];
    return r;
}
__device__ __forceinline__ float blockMax(float v) {
    __shared__ float sm[8];
    int lane = threadIdx.x & 31, w = threadIdx.x >> 5;
    v = warpMax(v);
    __syncthreads();
    if (lane == 0) sm[w] = v;
    __syncthreads();
    float r = -3.4e38f;
    #pragma unroll
    for (int i = 0; i < 8; i++) r = fmaxf(r, sm[i]);
    return r;
}

// ---------------- elementwise f32 -> fp16 hi/lo plane split (2 words/thread) ----------------
__global__ void split_k(const float* __restrict__ in, uint32_t* __restrict__ hi,
                        uint32_t* __restrict__ lo, int nWords) {
    int i = (blockIdx.x * 256 + threadIdx.x) * 2;
    if (i < nWords) {
        float4 v = *(const float4*)(in + 2 * (size_t)i);
        uint32_t h0, l0, h1, l1;
        splitpack(v.x, v.y, h0, l0);
        splitpack(v.z, v.w, h1, l1);
        *(uint2*)(hi + i) = make_uint2(h0, h1);
        if (lo) *(uint2*)(lo + i) = make_uint2(l0, l1);
    }
}
// hi-only variant for weights (B operands never need lo)
__global__ void split_hi_k(const float* __restrict__ in, uint32_t* __restrict__ hi, int nWords) {
    int i = (blockIdx.x * 256 + threadIdx.x) * 2;
    if (i < nWords) {
        float4 v = *(const float4*)(in + 2 * (size_t)i);
        *(uint2*)(hi + i) = make_uint2(pack_hi(v.x, v.y), pack_hi(v.z, v.w));
    }
}

// ---------------- embed + input layernorm -> f32 x ----------------
__global__ void embed_ln_k(const int* __restrict__ src, const float* __restrict__ emb,
                           const float* __restrict__ s, const float* __restrict__ b,
                           float* __restrict__ out) {
    int row = blockIdx.x, t = threadIdx.x;
    int tok = src[row];
    const float SC = 22.62741699796952f;
    float v0 = emb[(size_t)tok * E_DIM + t]       * SC;
    float v1 = emb[(size_t)tok * E_DIM + t + 256] * SC;
    float mean = blockSum(v0 + v1) * (1.f / E_DIM);
    float d0 = v0 - mean, d1 = v1 - mean;
    float var = blockSum(d0 * d0 + d1 * d1) * (1.f / E_DIM);
    float r = rsqrtf(var + 1e-5f);
    out[(size_t)row * E_DIM + t]       = d0 * r * s[t]       + b[t];
    out[(size_t)row * E_DIM + t + 256] = d1 * r * s[t + 256] + b[t + 256];
}

// ---------------- layernorm f32 -> split planes ----------------
__global__ void layernorm_split_k(const float* __restrict__ in, const float* __restrict__ s,
                                  const float* __restrict__ b,
                                  uint32_t* __restrict__ oh, uint32_t* __restrict__ ol) {
    int row = blockIdx.x, t = threadIdx.x;
    float2 v = *(const float2*)(in + (size_t)row * E_DIM + 2 * t);
    float mean = blockSum(v.x + v.y) * (1.f / E_DIM);
    float d0 = v.x - mean, d1 = v.y - mean;
    float var = blockSum(d0 * d0 + d1 * d1) * (1.f / E_DIM);
    float r = rsqrtf(var + 1e-5f);
    float y0 = d0 * r * s[2 * t]     + b[2 * t];
    float y1 = d1 * r * s[2 * t + 1] + b[2 * t + 1];
    uint32_t h, l;
    splitpack(y0, y1, h, l);
    oh[(size_t)row * 256 + t] = h;
    ol[(size_t)row * 256 + t] = l;
}

// ---------------- softmax (scale + rel bias + mask) -> split probs planes ----------------
__global__ void softmax_split_k(const float* __restrict__ qk, const float* __restrict__ qr,
                                uint32_t* __restrict__ ph, uint32_t* __restrict__ pl) {
    int bh = blockIdx.y, l = blockIdx.x, m = threadIdx.x;
    const float* row = qk + (size_t)bh * (S_LEN * S_LEN) + (size_t)l * S_LEN;
    float bias = qr[(size_t)bh * (S_LEN * 512) + (size_t)l * 512 + (m - l + 255)];
    float v = row[m] * 0.125f + bias + ((m > l) ? 1.0f : 0.0f);
    float mx = blockMax(v);
    float e = expf(v - mx);
    float sum = blockSum(e);
    float p = e / sum;
    float pn = __shfl_xor_sync(0xffffffffu, p, 1);
    if ((m & 1) == 0) {
        uint32_t h, lo;
        splitpack(p, pn, h, lo);
        size_t idx = (size_t)bh * (S_LEN * 128) + (size_t)l * 128 + (m >> 1);
        ph[idx] = h; pl[idx] = lo;
    }
}

// ---------------- mma / ldmatrix / cp.async primitives ----------------
#define MMA_F16(C, A0, A1, A2, A3, B0, B1)                                      \
    asm volatile("mma.sync.aligned.m16n8k16.row.col.f32.f16.f16.f32 "           \
                 "{%0,%1,%2,%3},{%4,%5,%6,%7},{%8,%9},{%0,%1,%2,%3};"           \
                 : "+f"(C[0]), "+f"(C[1]), "+f"(C[2]), "+f"(C[3])               \
                 : "r"(A0), "r"(A1), "r"(A2), "r"(A3), "r"(B0), "r"(B1))

__device__ __forceinline__ void ldsm4(uint32_t& r0, uint32_t& r1, uint32_t& r2, uint32_t& r3,
                                      uint32_t addr) {
    asm volatile("ldmatrix.sync.aligned.m8n8.x4.shared.b16 {%0,%1,%2,%3}, [%4];"
                 : "=r"(r0), "=r"(r1), "=r"(r2), "=r"(r3) : "r"(addr));
}

__device__ __forceinline__ void cp16w(uint32_t* dst, const uint32_t* src, bool pred) {
    uint32_t d = (uint32_t)__cvta_generic_to_shared(dst);
    int sz = pred ? 16 : 0;
    asm volatile("cp.async.cg.shared.global [%0], [%1], 16, %2;"
                 :: "r"(d), "l"(src), "r"(sz));
}

// smem geometry (words / bytes): 3 planes per stage (A-hi, A-lo, B-hi)
#define PLANE_W   (128 * 12)
#define PLANE_B   (PLANE_W * 4)
#define STAGE_W   (3 * PLANE_W)
#define STAGE_B   (3 * PLANE_B)
#define STAGES    3
#define SMEM_BYTES (STAGES * STAGE_B)   // 55296
#define NN_SMEM    (3 * PLANE_B)

// ---------------- fp16 2-term GEMM, 128x128 CTA tile, chunk k=16 (8 words) ----------------
// A: hi+lo planes [rows][Kw]; B: hi plane only.
// EPI: 0 = f32 out (+bias); 1 = f32 splitK atomicAdd (+bias at sk==0);
//      2 = planes out, bias + exact GELU; 3 = planes out (+bias).
template<int EPI, int NSPLIT>
__global__ __launch_bounds__(256, 2)
void bgemm(const uint32_t* __restrict__ Ah, const uint32_t* __restrict__ Al,
           const uint32_t* __restrict__ Bh,
           const float* __restrict__ bias,
           float* __restrict__ Cf, uint32_t* __restrict__ Ch, uint32_t* __restrict__ Cl,
           int M, int N, int Kw, int ldaw, int ldbw, int ldc,
           int aOffB, int aOffH, int bOffB, int bOffH, int cOffB, int cOffH) {
    extern __shared__ uint32_t smu[];   // [STAGES][3 planes][PLANE_W]

    int z = blockIdx.z;
    int sk = z % NSPLIT;
    int zz = z / NSPLIT;
    int zb = zz >> 3, zh = zz & 7;
    Ah += (size_t)zb * aOffB + (size_t)zh * aOffH;
    Al += (size_t)zb * aOffB + (size_t)zh * aOffH;
    Bh += (size_t)zb * bOffB + (size_t)zh * bOffH;
    size_t cAdj = (size_t)zb * cOffB + (size_t)zh * cOffH;
    if (EPI <= 1) Cf += cAdj; else { Ch += cAdj; Cl += cAdj; }

    int kLenW = Kw / NSPLIT;
    int kw0   = sk * kLenW;
    int nk    = kLenW >> 3;

    int tid  = threadIdx.x;
    int lane = tid & 31, wid = tid >> 5;
    int wm0 = (wid >> 2) * 64;
    int wn0 = (wid & 3) * 32;
    int g   = lane >> 2;
    int tg  = lane & 3;
    int row0 = blockIdx.y * 128, col0 = blockIdx.x * 128;

    int lrow = tid >> 1;
    int seg  = (tid & 1) * 4;

    uint32_t smBase = (uint32_t)__cvta_generic_to_shared(smu);
    uint32_t a_off = ((uint32_t)(wm0 + (lane & 15)) * 12 + ((lane & 16) ? 4 : 0)) * 4;
    uint32_t b_off = ((uint32_t)(wn0 + (lane & 7) + ((lane & 16) ? 8 : 0)) * 12
                      + ((lane & 8) ? 4 : 0)) * 4;

    float acc[4][4][4] = {};

    auto COMPUTE = [&](int buf) {
        uint32_t sb = smBase + (uint32_t)buf * STAGE_B;
        uint32_t aH = sb + a_off;
        uint32_t aL = aH + PLANE_B;
        uint32_t bH = sb + 2 * PLANE_B + b_off;
        uint32_t Bhf[4][2];
        ldsm4(Bhf[0][0], Bhf[0][1], Bhf[1][0], Bhf[1][1], bH);
        ldsm4(Bhf[2][0], Bhf[2][1], Bhf[3][0], Bhf[3][1], bH + 16 * 12 * 4);
        #pragma unroll
        for (int mi = 0; mi < 4; mi++) {
            uint32_t Af[4], Lf[4];
            ldsm4(Af[0], Af[1], Af[2], Af[3], aH + (uint32_t)mi * 16 * 12 * 4);
            ldsm4(Lf[0], Lf[1], Lf[2], Lf[3], aL + (uint32_t)mi * 16 * 12 * 4);
            #pragma unroll
            for (int ni = 0; ni < 4; ni++) {
                MMA_F16(acc[mi][ni], Af[0], Af[1], Af[2], Af[3], Bhf[ni][0], Bhf[ni][1]);
                MMA_F16(acc[mi][ni], Lf[0], Lf[1], Lf[2], Lf[3], Bhf[ni][0], Bhf[ni][1]);
            }
        }
    };

    auto LOADNT = [&](int chunk, int buf) {
        int kws = kw0 + (chunk << 3) + seg;
        uint32_t* st = smu + buf * STAGE_W;
        cp16w(st + lrow * 12 + seg,               Ah + (size_t)(row0 + lrow) * ldaw + kws, true);
        cp16w(st + PLANE_W + lrow * 12 + seg,     Al + (size_t)(row0 + lrow) * ldaw + kws, true);
        bool p = (col0 + lrow) < N;
        cp16w(st + 2 * PLANE_W + lrow * 12 + seg, Bh + (size_t)(col0 + lrow) * ldbw + kws, p);
    };
    int pre = (nk < STAGES - 1) ? nk : (STAGES - 1);
    for (int s = 0; s < pre; s++) {
        LOADNT(s, s);
        asm volatile("cp.async.commit_group;");
    }
    for (int i = 0; i < nk; i++) {
        int buf = i % STAGES;
        asm volatile("cp.async.wait_group %0;" :: "n"(STAGES - 2));
        __syncthreads();
        COMPUTE(buf);
        int nxt = i + STAGES - 1;
        if (nxt < nk) LOADNT(nxt, nxt % STAGES);
        asm volatile("cp.async.commit_group;");
    }

    // ---------------- epilogue ----------------
    #pragma unroll
    for (int mi = 0; mi < 4; mi++) {
        #pragma unroll
        for (int rr = 0; rr < 2; rr++) {
            int r = row0 + wm0 + mi * 16 + g + rr * 8;
            #pragma unroll
            for (int ni = 0; ni < 4; ni++) {
                int c = col0 + wn0 + ni * 8 + tg * 2;
                float v0 = acc[mi][ni][rr * 2];
                float v1 = acc[mi][ni][rr * 2 + 1];
                if (EPI == 0 && NSPLIT == 1) {
                    float* Crow = Cf + (size_t)r * ldc;
                    if (c + 1 < N) {
                        if (bias) { v0 += bias[c]; v1 += bias[c + 1]; }
                        *(float2*)&Crow[c] = make_float2(v0, v1);
                    } else if (c < N) {
                        if (bias) v0 += bias[c];
                        Crow[c] = v0;
                    }
                } else if (EPI == 1) {
                    float* Crow = Cf + (size_t)r * ldc;
                    if (bias && sk == 0) {
                        if (c < N)     v0 += bias[c];
                        if (c + 1 < N) v1 += bias[c + 1];
                    }
                    if (c < N)     atomicAdd(&Crow[c], v0);
                    if (c + 1 < N) atomicAdd(&Crow[c + 1], v1);
                } else if (EPI >= 2) {
                    if (c < N) {
                        if (bias) { v0 += bias[c]; v1 += bias[c + 1]; }
                        if (EPI == 2) {
                            v0 = 0.5f * v0 * (1.f + erff(v0 * 0.7071067811865476f));
                            v1 = 0.5f * v1 * (1.f + erff(v1 * 0.7071067811865476f));
                        }
                        uint32_t h, l;
                        splitpack(v0, v1, h, l);
                        size_t idx = (size_t)r * ldc + (c >> 1);
                        Ch[idx] = h; Cl[idx] = l;
                    }
                }
            }
        }
    }
}

// probs@V (NN): A planes [M][Kw], B hi plane [K][Nw] transposed by loader. Planes out.
__global__ __launch_bounds__(256, 2)
void bgemm_nn(const uint32_t* __restrict__ Ah, const uint32_t* __restrict__ Al,
              const uint32_t* __restrict__ Bh,
              uint32_t* __restrict__ Ch, uint32_t* __restrict__ Cl,
              int M, int N, int Kw, int ldaw, int ldbw, int ldc,
              int aOffB, int aOffH, int bOffB, int bOffH, int cOffB, int cOffH) {
    extern __shared__ uint32_t smu[];

    int z = blockIdx.z;
    int zb = z >> 3, zh = z & 7;
    Ah += (size_t)zb * aOffB + (size_t)zh * aOffH;
    Al += (size_t)zb * aOffB + (size_t)zh * aOffH;
    Bh += (size_t)zb * bOffB + (size_t)zh * bOffH;
    Ch += (size_t)zb * cOffB + (size_t)zh * cOffH;
    Cl += (size_t)zb * cOffB + (size_t)zh * cOffH;

    int nk = Kw >> 3;
    int tid  = threadIdx.x;
    int lane = tid & 31, wid = tid >> 5;
    int wm0 = (wid >> 2) * 64;
    int wn0 = (wid & 3) * 32;
    int g   = lane >> 2;
    int tg  = lane & 3;
    int row0 = blockIdx.y * 128, col0 = blockIdx.x * 128;

    int lrow = tid >> 1;
    int seg  = (tid & 1) * 4;

    uint32_t smBase = (uint32_t)__cvta_generic_to_shared(smu);
    uint32_t a_off = ((uint32_t)(wm0 + (lane & 15)) * 12 + ((lane & 16) ? 4 : 0)) * 4;
    uint32_t b_off = ((uint32_t)(wn0 + (lane & 7) + ((lane & 16) ? 8 : 0)) * 12
                      + ((lane & 8) ? 4 : 0)) * 4;

    float acc[4][4][4] = {};

    int nw = tid >> 3;
    int kw = tid & 7;
    for (int i = 0; i < nk; i++) {
        int kws = (i << 3);
        uint32_t w0h[2], w1h[2];
        #pragma unroll
        for (int u = 0; u < 2; u++) {
            int nwu = nw + u * 32;
            int k = (i << 4) + (kw << 1);
            bool valid = (2 * nwu + 1) < N;
            const uint32_t* sH = Bh + (size_t)k * ldbw + nwu;
            w0h[u] = valid ? sH[0] : 0u; w1h[u] = valid ? sH[ldbw] : 0u;
        }
        __syncthreads();
        cp16w(smu + lrow * 12 + seg,           Ah + (size_t)(row0 + lrow) * ldaw + kws + seg, true);
        cp16w(smu + PLANE_W + lrow * 12 + seg, Al + (size_t)(row0 + lrow) * ldaw + kws + seg, true);
        asm volatile("cp.async.commit_group;");
        #pragma unroll
        for (int u = 0; u < 2; u++) {
            int nwu = nw + u * 32;
            smu[2 * PLANE_W + (2 * nwu)     * 12 + kw] = (w0h[u] & 0xFFFFu) | (w1h[u] << 16);
            smu[2 * PLANE_W + (2 * nwu + 1) * 12 + kw] = (w0h[u] >> 16) | (w1h[u] & 0xFFFF0000u);
        }
        asm volatile("cp.async.wait_group 0;");
        __syncthreads();

        uint32_t aH = smBase + a_off;
        uint32_t aL = aH + PLANE_B;
        uint32_t bH = smBase + 2 * PLANE_B + b_off;
        uint32_t Bhf[4][2];
        ldsm4(Bhf[0][0], Bhf[0][1], Bhf[1][0], Bhf[1][1], bH);
        ldsm4(Bhf[2][0], Bhf[2][1], Bhf[3][0], Bhf[3][1], bH + 16 * 12 * 4);
        #pragma unroll
        for (int mi = 0; mi < 4; mi++) {
            uint32_t Af[4], Lf[4];
            ldsm4(Af[0], Af[1], Af[2], Af[3], aH + (uint32_t)mi * 16 * 12 * 4);
            ldsm4(Lf[0], Lf[1], Lf[2], Lf[3], aL + (uint32_t)mi * 16 * 12 * 4);
            #pragma unroll
            for (int ni = 0; ni < 4; ni++) {
                MMA_F16(acc[mi][ni], Af[0], Af[1], Af[2], Af[3], Bhf[ni][0], Bhf[ni][1]);
                MMA_F16(acc[mi][ni], Lf[0], Lf[1], Lf[2], Lf[3], Bhf[ni][0], Bhf[ni][1]);
            }
        }
    }

    #pragma unroll
    for (int mi = 0; mi < 4; mi++) {
        #pragma unroll
        for (int rr = 0; rr < 2; rr++) {
            int r = row0 + wm0 + mi * 16 + g + rr * 8;
            #pragma unroll
            for (int ni = 0; ni < 4; ni++) {
                int c = col0 + wn0 + ni * 8 + tg * 2;
                if (c < N) {
                    uint32_t h, l;
                    splitpack(acc[mi][ni][rr * 2], acc[mi][ni][rr * 2 + 1], h, l);
                    size_t idx = (size_t)r * ldc + (c >> 1);
                    Ch[idx] = h; Cl[idx] = l;
                }
            }
        }
    }
}

// ---------------- driver ----------------
extern "C" void kernel_launch(void* const* d_in, const int* in_sizes, int n_in,
                              void* d_out, int out_size) {
    const int*   src   = (const int*)  d_in[0];
    const float* emb   = (const float*)d_in[1];
    const float* rel   = (const float*)d_in[2];
    const float* nin_s = (const float*)d_in[3];
    const float* nin_b = (const float*)d_in[4];
    const float* inW   = (const float*)d_in[5];
    const float* inB   = (const float*)d_in[6];
    const float* outW  = (const float*)d_in[7];
    const float* outB  = (const float*)d_in[8];
    const float* ln1s  = (const float*)d_in[9];
    const float* ln1b  = (const float*)d_in[10];
    const float* ln2s  = (const float*)d_in[11];
    const float* ln2b  = (const float*)d_in[12];
    const float* w1    = (const float*)d_in[13];
    const float* b1    = (const float*)d_in[14];
    const float* w2    = (const float*)d_in[15];
    const float* b2    = (const float*)d_in[16];
    const float* nfs   = (const float*)d_in[17];
    const float* nfb   = (const float*)d_in[18];
    const float* decW  = (const float*)d_in[19];
    const float* decB  = (const float*)d_in[20];
    float* out = (float*)d_out;

    float *x, *qk, *qr;
    cudaGetSymbolAddress((void**)&x,  g_x);
    cudaGetSymbolAddress((void**)&qk, g_qk);
    cudaGetSymbolAddress((void**)&qr, g_qr);
    uint32_t *hH,*hL,*qkvH,*qkvL,*prH,*prL,*oH,*oL,*gH,*gL;
    uint32_t *WiH,*WoH,*W1H,*W2H,*WdH,*relH;
    cudaGetSymbolAddress((void**)&hH,   p_h_hi);   cudaGetSymbolAddress((void**)&hL,   p_h_lo);
    cudaGetSymbolAddress((void**)&qkvH, p_qkv_hi); cudaGetSymbolAddress((void**)&qkvL, p_qkv_lo);
    cudaGetSymbolAddress((void**)&prH,  p_pr_hi);  cudaGetSymbolAddress((void**)&prL,  p_pr_lo);
    cudaGetSymbolAddress((void**)&oH,   p_o_hi);   cudaGetSymbolAddress((void**)&oL,   p_o_lo);
    cudaGetSymbolAddress((void**)&gH,   p_g_hi);   cudaGetSymbolAddress((void**)&gL,   p_g_lo);
    cudaGetSymbolAddress((void**)&WiH,  p_Wi_hi);
    cudaGetSymbolAddress((void**)&WoH,  p_Wo_hi);
    cudaGetSymbolAddress((void**)&W1H,  p_W1_hi);
    cudaGetSymbolAddress((void**)&W2H,  p_W2_hi);
    cudaGetSymbolAddress((void**)&WdH,  p_Wd_hi);
    cudaGetSymbolAddress((void**)&relH, p_rel_hi);

    cudaFuncSetAttribute(bgemm<3,1>, cudaFuncAttributeMaxDynamicSharedMemorySize, SMEM_BYTES);
    cudaFuncSetAttribute(bgemm<0,1>, cudaFuncAttributeMaxDynamicSharedMemorySize, SMEM_BYTES);
    cudaFuncSetAttribute(bgemm<1,4>, cudaFuncAttributeMaxDynamicSharedMemorySize, SMEM_BYTES);
    cudaFuncSetAttribute(bgemm<2,1>, cudaFuncAttributeMaxDynamicSharedMemorySize, SMEM_BYTES);

    // weight splits: hi-only for B operands
    split_hi_k<<<(4*1536*256/2 + 255)/256, 256>>>(inW,  WiH, 4*1536*256);
    split_hi_k<<<(4*512*256/2  + 255)/256, 256>>>(outW, WoH, 4*512*256);
    split_hi_k<<<(4*2048*256/2 + 255)/256, 256>>>(w1,   W1H, 4*2048*256);
    split_hi_k<<<(4*512*1024/2 + 255)/256, 256>>>(w2,   W2H, 4*512*1024);
    split_hi_k<<<(V_DIM*256/2  + 255)/256, 256>>>(decW, WdH, V_DIM*256);
    split_hi_k<<<(511*256/2    + 255)/256, 256>>>(rel,  relH, 511*256);

    embed_ln_k<<<N_ROWS, 256>>>(src, emb, nin_s, nin_b, x);

    for (int l = 0; l < 4; l++) {
        const uint32_t* WiHl = WiH + (size_t)l * 1536 * 256;
        const uint32_t* WoHl = WoH + (size_t)l * 512 * 256;
        const uint32_t* W1Hl = W1H + (size_t)l * 2048 * 256;
        const uint32_t* W2Hl = W2H + (size_t)l * 512 * 1024;
        const float* inB_l  = inB  + (size_t)l * QKV_DIM;
        const float* outB_l = outB + (size_t)l * E_DIM;
        const float* b1_l   = b1   + (size_t)l * FF_DIM;
        const float* b2_l   = b2   + (size_t)l * E_DIM;

        layernorm_split_k<<<N_ROWS, 256>>>(x, ln1s + l*E_DIM, ln1b + l*E_DIM, hH, hL);

        // qkv planes = h @ inW^T + inB
        bgemm<3,1><<<dim3(12, 8, 1), 256, SMEM_BYTES>>>(hH, hL, WiHl, inB_l,
            (float*)0, qkvH, qkvL, N_ROWS, QKV_DIM, 256, 256, 256, 768,
            0,0, 0,0, 0,0);

        // scores f32 = Q @ K^T  (per bh; B = K hi plane)
        bgemm<0,1><<<dim3(2, 2, N_BH), 256, SMEM_BYTES>>>(qkvH, qkvL, qkvH + 256, (const float*)0,
            qk, (uint32_t*)0, (uint32_t*)0, S_LEN, S_LEN, 32, 768, 768, S_LEN,
            256*768, 32, 256*768, 32, 8*65536, 65536);

        // qr f32 = Q @ rel^T
        bgemm<0,1><<<dim3(4, 2, N_BH), 256, SMEM_BYTES>>>(qkvH, qkvL, relH, (const float*)0,
            qr, (uint32_t*)0, (uint32_t*)0, S_LEN, 511, 32, 768, 256, 512,
            256*768, 32, 0, 32, 8*131072, 131072);

        softmax_split_k<<<dim3(S_LEN, N_BH), 256>>>(qk, qr, prH, prL);

        // o planes = probs @ V  (NN; B = V hi plane)
        bgemm_nn<<<dim3(1, 2, N_BH), 256, NN_SMEM>>>(prH, prL, qkvH + 512,
            oH, oL, S_LEN, 64, 128, 128, 768, 256,
            8*32768, 32768, 256*768, 32, 65536, 32);

        // x += o @ outW^T + outB   (splitK 4, atomic)
        bgemm<1,4><<<dim3(4, 8, 4), 256, SMEM_BYTES>>>(oH, oL, WoHl, outB_l,
            x, (uint32_t*)0, (uint32_t*)0, N_ROWS, E_DIM, 256, 256, 256, E_DIM,
            0,0, 0,0, 0,0);

        layernorm_split_k<<<N_ROWS, 256>>>(x, ln2s + l*E_DIM, ln2b + l*E_DIM, hH, hL);

        // g planes = gelu(h @ w1^T + b1)
        bgemm<2,1><<<dim3(16, 8, 1), 256, SMEM_BYTES>>>(hH, hL, W1Hl, b1_l,
            (float*)0, gH, gL, N_ROWS, FF_DIM, 256, 256, 256, 1024,
            0,0, 0,0, 0,0);

        // x += g @ w2^T + b2   (splitK 4, atomic)
        bgemm<1,4><<<dim3(4, 8, 4), 256, SMEM_BYTES>>>(gH, gL, W2Hl, b2_l,
            x, (uint32_t*)0, (uint32_t*)0, N_ROWS, E_DIM, 1024, 1024, 1024, E_DIM,
            0,0, 0,0, 0,0);
    }

    layernorm_split_k<<<N_ROWS, 256>>>(x, nfs, nfb, hH, hL);

    // out f32 = h @ dec_w^T + dec_b
    bgemm<0,1><<<dim3(250, 8, 1), 256, SMEM_BYTES>>>(hH, hL, WdH, decB,
        out, (uint32_t*)0, (uint32_t*)0, N_ROWS, V_DIM, 256, 256, 256, V_DIM,
        0,0, 0,0, 0,0);
}

// round 8
// speedup vs baseline: 3.0977x; 1.1232x over previous
#include <cuda_runtime.h>
#include <cuda_fp16.h>
#include <math.h>
#include <stdint.h>

// ---------------- problem constants ----------------
#define N_ROWS   1024
#define E_DIM    512
#define QKV_DIM  1536
#define FF_DIM   2048
#define V_DIM    32000
#define N_BH     32
#define S_LEN    256

// ---------------- f32 scratch ----------------
__device__ float g_x [N_ROWS * E_DIM];
__device__ float g_qk[N_BH * S_LEN * S_LEN];
__device__ float g_qr[N_BH * S_LEN * 512];

// ---------------- packed fp16 planes (word = 2 consecutive-k halves) ----------------
__device__ uint32_t p_h_hi  [N_ROWS * 256],  p_h_lo  [N_ROWS * 256];
__device__ uint32_t p_qkv_hi[N_ROWS * 768];
__device__ uint32_t p_pr_hi [N_BH * S_LEN * 128];
__device__ uint32_t p_o_hi  [N_ROWS * 256],  p_o_lo  [N_ROWS * 256];
__device__ uint32_t p_g_hi  [N_ROWS * 1024], p_g_lo  [N_ROWS * 1024];
__device__ uint32_t p_Wi_hi [4 * 1536 * 256];
__device__ uint32_t p_Wo_hi [4 * 512 * 256];
__device__ uint32_t p_W1_hi [4 * 2048 * 256];
__device__ uint32_t p_W2_hi [4 * 512 * 1024];
__device__ uint32_t p_Wd_hi [V_DIM * 256];
__device__ uint32_t p_rel_hi[511 * 256];

// ---------------- helpers ----------------
__device__ __forceinline__ void splitpack(float v0, float v1, uint32_t& hi, uint32_t& lo) {
    __half h0 = __float2half_rn(v0);
    __half h1 = __float2half_rn(v1);
    float r0 = v0 - __half2float(h0);
    float r1 = v1 - __half2float(h1);
    __half l0 = __float2half_rn(r0);
    __half l1 = __float2half_rn(r1);
    hi = (uint32_t)__half_as_ushort(h0) | ((uint32_t)__half_as_ushort(h1) << 16);
    lo = (uint32_t)__half_as_ushort(l0) | ((uint32_t)__half_as_ushort(l1) << 16);
}
__device__ __forceinline__ uint32_t pack_hi(float v0, float v1) {
    __half h0 = __float2half_rn(v0);
    __half h1 = __float2half_rn(v1);
    return (uint32_t)__half_as_ushort(h0) | ((uint32_t)__half_as_ushort(h1) << 16);
}

__device__ __forceinline__ float warpSum(float v) {
    #pragma unroll
    for (int o = 16; o; o >>= 1) v += __shfl_xor_sync(0xffffffffu, v, o);
    return v;
}
__device__ __forceinline__ float warpMax(float v) {
    #pragma unroll
    for (int o = 16; o; o >>= 1) v = fmaxf(v, __shfl_xor_sync(0xffffffffu, v, o));
    return v;
}
__device__ __forceinline__ float blockSum(float v) {
    __shared__ float sm[8];
    int lane = threadIdx.x & 31, w = threadIdx.x >> 5;
    v = warpSum(v);
    __syncthreads();
    if (lane == 0) sm[w] = v;
    __syncthreads();
    float r = 0.f;
    #pragma unroll
    for (int i = 0; i < 8; i++) r += sm[i];
    return r;
}
__device__ __forceinline__ float blockMax(float v) {
    __shared__ float sm[8];
    int lane = threadIdx.x & 31, w = threadIdx.x >> 5;
    v = warpMax(v);
    __syncthreads();
    if (lane == 0) sm[w] = v;
    __syncthreads();
    float r = -3.4e38f;
    #pragma unroll
    for (int i = 0; i < 8; i++) r = fmaxf(r, sm[i]);
    return r;
}

// ---------------- f32 -> fp16 hi plane (4 words / 16B per thread) ----------------
__global__ void split_hi_k(const float* __restrict__ in, uint32_t* __restrict__ hi, int nWords) {
    int i = (blockIdx.x * 256 + threadIdx.x) * 4;
    if (i < nWords) {
        float4 a = *(const float4*)(in + 2 * (size_t)i);
        float4 b = *(const float4*)(in + 2 * (size_t)i + 4);
        uint4 o;
        o.x = pack_hi(a.x, a.y); o.y = pack_hi(a.z, a.w);
        o.z = pack_hi(b.x, b.y); o.w = pack_hi(b.z, b.w);
        *(uint4*)(hi + i) = o;
    }
}

// ---------------- embed + input layernorm -> f32 x ----------------
__global__ void embed_ln_k(const int* __restrict__ src, const float* __restrict__ emb,
                           const float* __restrict__ s, const float* __restrict__ b,
                           float* __restrict__ out) {
    int row = blockIdx.x, t = threadIdx.x;
    int tok = src[row];
    const float SC = 22.62741699796952f;
    float v0 = emb[(size_t)tok * E_DIM + t]       * SC;
    float v1 = emb[(size_t)tok * E_DIM + t + 256] * SC;
    float mean = blockSum(v0 + v1) * (1.f / E_DIM);
    float d0 = v0 - mean, d1 = v1 - mean;
    float var = blockSum(d0 * d0 + d1 * d1) * (1.f / E_DIM);
    float r = rsqrtf(var + 1e-5f);
    out[(size_t)row * E_DIM + t]       = d0 * r * s[t]       + b[t];
    out[(size_t)row * E_DIM + t + 256] = d1 * r * s[t + 256] + b[t + 256];
}

// ---------------- layernorm f32 -> split planes ----------------
__global__ void layernorm_split_k(const float* __restrict__ in, const float* __restrict__ s,
                                  const float* __restrict__ b,
                                  uint32_t* __restrict__ oh, uint32_t* __restrict__ ol) {
    int row = blockIdx.x, t = threadIdx.x;
    float2 v = *(const float2*)(in + (size_t)row * E_DIM + 2 * t);
    float mean = blockSum(v.x + v.y) * (1.f / E_DIM);
    float d0 = v.x - mean, d1 = v.y - mean;
    float var = blockSum(d0 * d0 + d1 * d1) * (1.f / E_DIM);
    float r = rsqrtf(var + 1e-5f);
    float y0 = d0 * r * s[2 * t]     + b[2 * t];
    float y1 = d1 * r * s[2 * t + 1] + b[2 * t + 1];
    uint32_t h, l;
    splitpack(y0, y1, h, l);
    oh[(size_t)row * 256 + t] = h;
    ol[(size_t)row * 256 + t] = l;
}

// ---------------- softmax (scale + rel bias + mask) -> hi probs plane ----------------
__global__ void softmax_split_k(const float* __restrict__ qk, const float* __restrict__ qr,
                                uint32_t* __restrict__ ph) {
    int bh = blockIdx.y, l = blockIdx.x, m = threadIdx.x;
    const float* row = qk + (size_t)bh * (S_LEN * S_LEN) + (size_t)l * S_LEN;
    float bias = qr[(size_t)bh * (S_LEN * 512) + (size_t)l * 512 + (m - l + 255)];
    float v = row[m] * 0.125f + bias + ((m > l) ? 1.0f : 0.0f);
    float mx = blockMax(v);
    float e = expf(v - mx);
    float sum = blockSum(e);
    float p = e / sum;
    float pn = __shfl_xor_sync(0xffffffffu, p, 1);
    if ((m & 1) == 0) {
        size_t idx = (size_t)bh * (S_LEN * 128) + (size_t)l * 128 + (m >> 1);
        ph[idx] = pack_hi(p, pn);
    }
}

// ---------------- mma / ldmatrix / cp.async primitives ----------------
#define MMA_F16(C, A0, A1, A2, A3, B0, B1)                                      \
    asm volatile("mma.sync.aligned.m16n8k16.row.col.f32.f16.f16.f32 "           \
                 "{%0,%1,%2,%3},{%4,%5,%6,%7},{%8,%9},{%0,%1,%2,%3};"           \
                 : "+f"(C[0]), "+f"(C[1]), "+f"(C[2]), "+f"(C[3])               \
                 : "r"(A0), "r"(A1), "r"(A2), "r"(A3), "r"(B0), "r"(B1))

__device__ __forceinline__ void ldsm4(uint32_t& r0, uint32_t& r1, uint32_t& r2, uint32_t& r3,
                                      uint32_t addr) {
    asm volatile("ldmatrix.sync.aligned.m8n8.x4.shared.b16 {%0,%1,%2,%3}, [%4];"
                 : "=r"(r0), "=r"(r1), "=r"(r2), "=r"(r3) : "r"(addr));
}

__device__ __forceinline__ void cp16w(uint32_t* dst, const uint32_t* src, bool pred) {
    uint32_t d = (uint32_t)__cvta_generic_to_shared(dst);
    int sz = pred ? 16 : 0;
    asm volatile("cp.async.cg.shared.global [%0], [%1], 16, %2;"
                 :: "r"(d), "l"(src), "r"(sz));
}

// smem geometry
#define PLANE_W   (128 * 12)
#define PLANE_B   (PLANE_W * 4)
#define STAGES    3
#define SMEM3     (STAGES * 3 * PLANE_B)   // 55296 (2-term: A-hi, A-lo, B-hi)
#define SMEM2     (STAGES * 2 * PLANE_B)   // 36864 (1-term: A-hi, B-hi)
#define NN_SMEM   (2 * PLANE_B)

// ---------------- fp16 GEMM, 128x128 CTA tile, chunk k=16 (8 words) ----------------
// ALO=1: A has hi+lo planes (2-term); ALO=0: hi only (1-term). B: hi plane only.
// EPI: 0 = f32 out (+bias); 1 = f32 splitK atomicAdd (+bias at sk==0);
//      2 = planes out, bias + exact GELU; 3 = planes out (+bias). EPI>=2: Cl may be null.
template<int EPI, int NSPLIT, int ALO>
__global__ __launch_bounds__(256, 2)
void bgemm(const uint32_t* __restrict__ Ah, const uint32_t* __restrict__ Al,
           const uint32_t* __restrict__ Bh,
           const float* __restrict__ bias,
           float* __restrict__ Cf, uint32_t* __restrict__ Ch, uint32_t* __restrict__ Cl,
           int M, int N, int Kw, int ldaw, int ldbw, int ldc,
           int aOffB, int aOffH, int bOffB, int bOffH, int cOffB, int cOffH) {
    extern __shared__ uint32_t smu[];
    constexpr int NPL   = 2 + ALO;
    constexpr int STW   = NPL * PLANE_W;
    constexpr int STB   = NPL * PLANE_B;
    constexpr int BOFFW = (1 + ALO) * PLANE_W;
    constexpr int BOFFB = (1 + ALO) * PLANE_B;

    int z = blockIdx.z;
    int sk = z % NSPLIT;
    int zz = z / NSPLIT;
    int zb = zz >> 3, zh = zz & 7;
    Ah += (size_t)zb * aOffB + (size_t)zh * aOffH;
    if (ALO) Al += (size_t)zb * aOffB + (size_t)zh * aOffH;
    Bh += (size_t)zb * bOffB + (size_t)zh * bOffH;
    size_t cAdj = (size_t)zb * cOffB + (size_t)zh * cOffH;
    if (EPI <= 1) Cf += cAdj; else { Ch += cAdj; if (Cl) Cl += cAdj; }

    int kLenW = Kw / NSPLIT;
    int kw0   = sk * kLenW;
    int nk    = kLenW >> 3;

    int tid  = threadIdx.x;
    int lane = tid & 31, wid = tid >> 5;
    int wm0 = (wid >> 2) * 64;
    int wn0 = (wid & 3) * 32;
    int g   = lane >> 2;
    int tg  = lane & 3;
    int row0 = blockIdx.y * 128, col0 = blockIdx.x * 128;

    int lrow = tid >> 1;
    int seg  = (tid & 1) * 4;

    uint32_t smBase = (uint32_t)__cvta_generic_to_shared(smu);
    uint32_t a_off = ((uint32_t)(wm0 + (lane & 15)) * 12 + ((lane & 16) ? 4 : 0)) * 4;
    uint32_t b_off = ((uint32_t)(wn0 + (lane & 7) + ((lane & 16) ? 8 : 0)) * 12
                      + ((lane & 8) ? 4 : 0)) * 4;

    float acc[4][4][4] = {};

    auto COMPUTE = [&](int buf) {
        uint32_t sb = smBase + (uint32_t)buf * STB;
        uint32_t aH = sb + a_off;
        uint32_t aL = aH + PLANE_B;
        uint32_t bH = sb + BOFFB + b_off;
        uint32_t Bhf[4][2];
        ldsm4(Bhf[0][0], Bhf[0][1], Bhf[1][0], Bhf[1][1], bH);
        ldsm4(Bhf[2][0], Bhf[2][1], Bhf[3][0], Bhf[3][1], bH + 16 * 12 * 4);
        #pragma unroll
        for (int mi = 0; mi < 4; mi++) {
            uint32_t Af[4];
            ldsm4(Af[0], Af[1], Af[2], Af[3], aH + (uint32_t)mi * 16 * 12 * 4);
            uint32_t Lf[4];
            if (ALO) ldsm4(Lf[0], Lf[1], Lf[2], Lf[3], aL + (uint32_t)mi * 16 * 12 * 4);
            #pragma unroll
            for (int ni = 0; ni < 4; ni++) {
                MMA_F16(acc[mi][ni], Af[0], Af[1], Af[2], Af[3], Bhf[ni][0], Bhf[ni][1]);
                if (ALO)
                    MMA_F16(acc[mi][ni], Lf[0], Lf[1], Lf[2], Lf[3], Bhf[ni][0], Bhf[ni][1]);
            }
        }
    };

    auto LOADNT = [&](int chunk, int buf) {
        int kws = kw0 + (chunk << 3) + seg;
        uint32_t* st = smu + buf * STW;
        cp16w(st + lrow * 12 + seg, Ah + (size_t)(row0 + lrow) * ldaw + kws, true);
        if (ALO)
            cp16w(st + PLANE_W + lrow * 12 + seg, Al + (size_t)(row0 + lrow) * ldaw + kws, true);
        bool p = (col0 + lrow) < N;
        cp16w(st + BOFFW + lrow * 12 + seg, Bh + (size_t)(col0 + lrow) * ldbw + kws, p);
    };
    int pre = (nk < STAGES - 1) ? nk : (STAGES - 1);
    for (int s = 0; s < pre; s++) {
        LOADNT(s, s);
        asm volatile("cp.async.commit_group;");
    }
    for (int i = 0; i < nk; i++) {
        int buf = i % STAGES;
        asm volatile("cp.async.wait_group %0;" :: "n"(STAGES - 2));
        __syncthreads();
        COMPUTE(buf);
        int nxt = i + STAGES - 1;
        if (nxt < nk) LOADNT(nxt, nxt % STAGES);
        asm volatile("cp.async.commit_group;");
    }

    // ---------------- epilogue ----------------
    #pragma unroll
    for (int mi = 0; mi < 4; mi++) {
        #pragma unroll
        for (int rr = 0; rr < 2; rr++) {
            int r = row0 + wm0 + mi * 16 + g + rr * 8;
            #pragma unroll
            for (int ni = 0; ni < 4; ni++) {
                int c = col0 + wn0 + ni * 8 + tg * 2;
                float v0 = acc[mi][ni][rr * 2];
                float v1 = acc[mi][ni][rr * 2 + 1];
                if (EPI == 0 && NSPLIT == 1) {
                    float* Crow = Cf + (size_t)r * ldc;
                    if (c + 1 < N) {
                        if (bias) { v0 += bias[c]; v1 += bias[c + 1]; }
                        *(float2*)&Crow[c] = make_float2(v0, v1);
                    } else if (c < N) {
                        if (bias) v0 += bias[c];
                        Crow[c] = v0;
                    }
                } else if (EPI == 1) {
                    float* Crow = Cf + (size_t)r * ldc;
                    if (bias && sk == 0) {
                        if (c < N)     v0 += bias[c];
                        if (c + 1 < N) v1 += bias[c + 1];
                    }
                    if (c < N)     atomicAdd(&Crow[c], v0);
                    if (c + 1 < N) atomicAdd(&Crow[c + 1], v1);
                } else if (EPI >= 2) {
                    if (c < N) {
                        if (bias) { v0 += bias[c]; v1 += bias[c + 1]; }
                        if (EPI == 2) {
                            v0 = 0.5f * v0 * (1.f + erff(v0 * 0.7071067811865476f));
                            v1 = 0.5f * v1 * (1.f + erff(v1 * 0.7071067811865476f));
                        }
                        uint32_t h, l;
                        splitpack(v0, v1, h, l);
                        size_t idx = (size_t)r * ldc + (c >> 1);
                        Ch[idx] = h;
                        if (Cl) Cl[idx] = l;
                    }
                }
            }
        }
    }
}

// probs@V (NN): A hi plane [M][Kw], B hi plane [K][Nw] transposed by loader. Planes out hi+lo.
__global__ __launch_bounds__(256, 2)
void bgemm_nn(const uint32_t* __restrict__ Ah, const uint32_t* __restrict__ Bh,
              uint32_t* __restrict__ Ch, uint32_t* __restrict__ Cl,
              int M, int N, int Kw, int ldaw, int ldbw, int ldc,
              int aOffB, int aOffH, int bOffB, int bOffH, int cOffB, int cOffH) {
    extern __shared__ uint32_t smu[];

    int z = blockIdx.z;
    int zb = z >> 3, zh = z & 7;
    Ah += (size_t)zb * aOffB + (size_t)zh * aOffH;
    Bh += (size_t)zb * bOffB + (size_t)zh * bOffH;
    Ch += (size_t)zb * cOffB + (size_t)zh * cOffH;
    Cl += (size_t)zb * cOffB + (size_t)zh * cOffH;

    int nk = Kw >> 3;
    int tid  = threadIdx.x;
    int lane = tid & 31, wid = tid >> 5;
    int wm0 = (wid >> 2) * 64;
    int wn0 = (wid & 3) * 32;
    int g   = lane >> 2;
    int tg  = lane & 3;
    int row0 = blockIdx.y * 128, col0 = blockIdx.x * 128;

    int lrow = tid >> 1;
    int seg  = (tid & 1) * 4;

    uint32_t smBase = (uint32_t)__cvta_generic_to_shared(smu);
    uint32_t a_off = ((uint32_t)(wm0 + (lane & 15)) * 12 + ((lane & 16) ? 4 : 0)) * 4;
    uint32_t b_off = ((uint32_t)(wn0 + (lane & 7) + ((lane & 16) ? 8 : 0)) * 12
                      + ((lane & 8) ? 4 : 0)) * 4;

    float acc[4][4][4] = {};

    int nw = tid >> 3;
    int kw = tid & 7;
    for (int i = 0; i < nk; i++) {
        int kws = (i << 3);
        uint32_t w0h[2], w1h[2];
        #pragma unroll
        for (int u = 0; u < 2; u++) {
            int nwu = nw + u * 32;
            int k = (i << 4) + (kw << 1);
            bool valid = (2 * nwu + 1) < N;
            const uint32_t* sH = Bh + (size_t)k * ldbw + nwu;
            w0h[u] = valid ? sH[0] : 0u; w1h[u] = valid ? sH[ldbw] : 0u;
        }
        __syncthreads();
        cp16w(smu + lrow * 12 + seg, Ah + (size_t)(row0 + lrow) * ldaw + kws + seg, true);
        asm volatile("cp.async.commit_group;");
        #pragma unroll
        for (int u = 0; u < 2; u++) {
            int nwu = nw + u * 32;
            smu[PLANE_W + (2 * nwu)     * 12 + kw] = (w0h[u] & 0xFFFFu) | (w1h[u] << 16);
            smu[PLANE_W + (2 * nwu + 1) * 12 + kw] = (w0h[u] >> 16) | (w1h[u] & 0xFFFF0000u);
        }
        asm volatile("cp.async.wait_group 0;");
        __syncthreads();

        uint32_t aH = smBase + a_off;
        uint32_t bH = smBase + PLANE_B + b_off;
        uint32_t Bhf[4][2];
        ldsm4(Bhf[0][0], Bhf[0][1], Bhf[1][0], Bhf[1][1], bH);
        ldsm4(Bhf[2][0], Bhf[2][1], Bhf[3][0], Bhf[3][1], bH + 16 * 12 * 4);
        #pragma unroll
        for (int mi = 0; mi < 4; mi++) {
            uint32_t Af[4];
            ldsm4(Af[0], Af[1], Af[2], Af[3], aH + (uint32_t)mi * 16 * 12 * 4);
            #pragma unroll
            for (int ni = 0; ni < 4; ni++)
                MMA_F16(acc[mi][ni], Af[0], Af[1], Af[2], Af[3], Bhf[ni][0], Bhf[ni][1]);
        }
    }

    #pragma unroll
    for (int mi = 0; mi < 4; mi++) {
        #pragma unroll
        for (int rr = 0; rr < 2; rr++) {
            int r = row0 + wm0 + mi * 16 + g + rr * 8;
            #pragma unroll
            for (int ni = 0; ni < 4; ni++) {
                int c = col0 + wn0 + ni * 8 + tg * 2;
                if (c < N) {
                    uint32_t h, l;
                    splitpack(acc[mi][ni][rr * 2], acc[mi][ni][rr * 2 + 1], h, l);
                    size_t idx = (size_t)r * ldc + (c >> 1);
                    Ch[idx] = h; Cl[idx] = l;
                }
            }
        }
    }
}

// ---------------- driver ----------------
extern "C" void kernel_launch(void* const* d_in, const int* in_sizes, int n_in,
                              void* d_out, int out_size) {
    const int*   src   = (const int*)  d_in[0];
    const float* emb   = (const float*)d_in[1];
    const float* rel   = (const float*)d_in[2];
    const float* nin_s = (const float*)d_in[3];
    const float* nin_b = (const float*)d_in[4];
    const float* inW   = (const float*)d_in[5];
    const float* inB   = (const float*)d_in[6];
    const float* outW  = (const float*)d_in[7];
    const float* outB  = (const float*)d_in[8];
    const float* ln1s  = (const float*)d_in[9];
    const float* ln1b  = (const float*)d_in[10];
    const float* ln2s  = (const float*)d_in[11];
    const float* ln2b  = (const float*)d_in[12];
    const float* w1    = (const float*)d_in[13];
    const float* b1    = (const float*)d_in[14];
    const float* w2    = (const float*)d_in[15];
    const float* b2    = (const float*)d_in[16];
    const float* nfs   = (const float*)d_in[17];
    const float* nfb   = (const float*)d_in[18];
    const float* decW  = (const float*)d_in[19];
    const float* decB  = (const float*)d_in[20];
    float* out = (float*)d_out;

    float *x, *qk, *qr;
    cudaGetSymbolAddress((void**)&x,  g_x);
    cudaGetSymbolAddress((void**)&qk, g_qk);
    cudaGetSymbolAddress((void**)&qr, g_qr);
    uint32_t *hH,*hL,*qkvH,*prH,*oH,*oL,*gH,*gL;
    uint32_t *WiH,*WoH,*W1H,*W2H,*WdH,*relH;
    cudaGetSymbolAddress((void**)&hH,   p_h_hi);   cudaGetSymbolAddress((void**)&hL,   p_h_lo);
    cudaGetSymbolAddress((void**)&qkvH, p_qkv_hi);
    cudaGetSymbolAddress((void**)&prH,  p_pr_hi);
    cudaGetSymbolAddress((void**)&oH,   p_o_hi);   cudaGetSymbolAddress((void**)&oL,   p_o_lo);
    cudaGetSymbolAddress((void**)&gH,   p_g_hi);   cudaGetSymbolAddress((void**)&gL,   p_g_lo);
    cudaGetSymbolAddress((void**)&WiH,  p_Wi_hi);
    cudaGetSymbolAddress((void**)&WoH,  p_Wo_hi);
    cudaGetSymbolAddress((void**)&W1H,  p_W1_hi);
    cudaGetSymbolAddress((void**)&W2H,  p_W2_hi);
    cudaGetSymbolAddress((void**)&WdH,  p_Wd_hi);
    cudaGetSymbolAddress((void**)&relH, p_rel_hi);

    cudaFuncSetAttribute(bgemm<3,1,1>, cudaFuncAttributeMaxDynamicSharedMemorySize, SMEM3);
    cudaFuncSetAttribute(bgemm<0,1,0>, cudaFuncAttributeMaxDynamicSharedMemorySize, SMEM2);
    cudaFuncSetAttribute(bgemm<1,4,1>, cudaFuncAttributeMaxDynamicSharedMemorySize, SMEM3);
    cudaFuncSetAttribute(bgemm<2,1,1>, cudaFuncAttributeMaxDynamicSharedMemorySize, SMEM3);

    // weight splits (hi-only, 16B/thread)
    split_hi_k<<<(4*1536*256/4 + 255)/256, 256>>>(inW,  WiH, 4*1536*256);
    split_hi_k<<<(4*512*256/4  + 255)/256, 256>>>(outW, WoH, 4*512*256);
    split_hi_k<<<(4*2048*256/4 + 255)/256, 256>>>(w1,   W1H, 4*2048*256);
    split_hi_k<<<(4*512*1024/4 + 255)/256, 256>>>(w2,   W2H, 4*512*1024);
    split_hi_k<<<(V_DIM*256/4  + 255)/256, 256>>>(decW, WdH, V_DIM*256);
    split_hi_k<<<(511*256/4    + 255)/256, 256>>>(rel,  relH, 511*256);

    embed_ln_k<<<N_ROWS, 256>>>(src, emb, nin_s, nin_b, x);

    for (int l = 0; l < 4; l++) {
        const uint32_t* WiHl = WiH + (size_t)l * 1536 * 256;
        const uint32_t* WoHl = WoH + (size_t)l * 512 * 256;
        const uint32_t* W1Hl = W1H + (size_t)l * 2048 * 256;
        const uint32_t* W2Hl = W2H + (size_t)l * 512 * 1024;
        const float* inB_l  = inB  + (size_t)l * QKV_DIM;
        const float* outB_l = outB + (size_t)l * E_DIM;
        const float* b1_l   = b1   + (size_t)l * FF_DIM;
        const float* b2_l   = b2   + (size_t)l * E_DIM;

        layernorm_split_k<<<N_ROWS, 256>>>(x, ln1s + l*E_DIM, ln1b + l*E_DIM, hH, hL);

        // qkv hi plane = h @ inW^T + inB   (2-term A)
        bgemm<3,1,1><<<dim3(12, 8, 1), 256, SMEM3>>>(hH, hL, WiHl, inB_l,
            (float*)0, qkvH, (uint32_t*)0, N_ROWS, QKV_DIM, 256, 256, 256, 768,
            0,0, 0,0, 0,0);

        // scores f32 = Q @ K^T  (1-term)
        bgemm<0,1,0><<<dim3(2, 2, N_BH), 256, SMEM2>>>(qkvH, (const uint32_t*)0, qkvH + 256,
            (const float*)0, qk, (uint32_t*)0, (uint32_t*)0,
            S_LEN, S_LEN, 32, 768, 768, S_LEN,
            256*768, 32, 256*768, 32, 8*65536, 65536);

        // qr f32 = Q @ rel^T  (1-term)
        bgemm<0,1,0><<<dim3(4, 2, N_BH), 256, SMEM2>>>(qkvH, (const uint32_t*)0, relH,
            (const float*)0, qr, (uint32_t*)0, (uint32_t*)0,
            S_LEN, 511, 32, 768, 256, 512,
            256*768, 32, 0, 32, 8*131072, 131072);

        softmax_split_k<<<dim3(S_LEN, N_BH), 256>>>(qk, qr, prH);

        // o planes = probs @ V  (NN, 1-term)
        bgemm_nn<<<dim3(1, 2, N_BH), 256, NN_SMEM>>>(prH, qkvH + 512,
            oH, oL, S_LEN, 64, 128, 128, 768, 256,
            8*32768, 32768, 256*768, 32, 65536, 32);

        // x += o @ outW^T + outB   (splitK 4, 2-term A)
        bgemm<1,4,1><<<dim3(4, 8, 4), 256, SMEM3>>>(oH, oL, WoHl, outB_l,
            x, (uint32_t*)0, (uint32_t*)0, N_ROWS, E_DIM, 256, 256, 256, E_DIM,
            0,0, 0,0, 0,0);

        layernorm_split_k<<<N_ROWS, 256>>>(x, ln2s + l*E_DIM, ln2b + l*E_DIM, hH, hL);

        // g planes = gelu(h @ w1^T + b1)  (2-term A)
        bgemm<2,1,1><<<dim3(16, 8, 1), 256, SMEM3>>>(hH, hL, W1Hl, b1_l,
            (float*)0, gH, gL, N_ROWS, FF_DIM, 256, 256, 256, 1024,
            0,0, 0,0, 0,0);

        // x += g @ w2^T + b2   (splitK 4, 2-term A)
        bgemm<1,4,1><<<dim3(4, 8, 4), 256, SMEM3>>>(gH, gL, W2Hl, b2_l,
            x, (uint32_t*)0, (uint32_t*)0, N_ROWS, E_DIM, 1024, 1024, 1024, E_DIM,
            0,0, 0,0, 0,0);
    }

    layernorm_split_k<<<N_ROWS, 256>>>(x, nfs, nfb, hH, hL);

    // out f32 = h @ dec_w^T + dec_b   (1-term: decoder A hi only)
    bgemm<0,1,0><<<dim3(250, 8, 1), 256, SMEM2>>>(hH, (const uint32_t*)0, WdH, decB,
        out, (uint32_t*)0, (uint32_t*)0, N_ROWS, V_DIM, 256, 256, 256, V_DIM,
        0,0, 0,0, 0,0);
}

// round 9
// speedup vs baseline: 3.1731x; 1.0243x over previous
#include <cuda_runtime.h>
#include <cuda_fp16.h>
#include <math.h>
#include <stdint.h>

// ---------------- problem constants ----------------
#define N_ROWS   1024
#define E_DIM    512
#define QKV_DIM  1536
#define FF_DIM   2048
#define V_DIM    32000
#define N_BH     32
#define S_LEN    256

// ---------------- f32 scratch ----------------
__device__ float g_x [N_ROWS * E_DIM];
__device__ float g_qr[N_BH * S_LEN * 512];

// ---------------- packed fp16 planes (word = 2 consecutive-k halves) ----------------
__device__ uint32_t p_h_hi  [N_ROWS * 256],  p_h_lo  [N_ROWS * 256];
__device__ uint32_t p_qkv_hi[N_ROWS * 768];
__device__ uint32_t p_pr_hi [N_BH * S_LEN * 128];
__device__ uint32_t p_vT    [N_BH * 64 * 128];
__device__ uint32_t p_o_hi  [N_ROWS * 256],  p_o_lo  [N_ROWS * 256];
__device__ uint32_t p_g_hi  [N_ROWS * 1024], p_g_lo  [N_ROWS * 1024];
__device__ uint32_t p_Wi_hi [4 * 1536 * 256];
__device__ uint32_t p_Wo_hi [4 * 512 * 256];
__device__ uint32_t p_W1_hi [4 * 2048 * 256];
__device__ uint32_t p_W2_hi [4 * 512 * 1024];
__device__ uint32_t p_Wd_hi [V_DIM * 256];
__device__ uint32_t p_rel_hi[511 * 256];

// ---------------- helpers ----------------
__device__ __forceinline__ void splitpack(float v0, float v1, uint32_t& hi, uint32_t& lo) {
    __half h0 = __float2half_rn(v0);
    __half h1 = __float2half_rn(v1);
    float r0 = v0 - __half2float(h0);
    float r1 = v1 - __half2float(h1);
    __half l0 = __float2half_rn(r0);
    __half l1 = __float2half_rn(r1);
    hi = (uint32_t)__half_as_ushort(h0) | ((uint32_t)__half_as_ushort(h1) << 16);
    lo = (uint32_t)__half_as_ushort(l0) | ((uint32_t)__half_as_ushort(l1) << 16);
}
__device__ __forceinline__ uint32_t pack_hi(float v0, float v1) {
    __half h0 = __float2half_rn(v0);
    __half h1 = __float2half_rn(v1);
    return (uint32_t)__half_as_ushort(h0) | ((uint32_t)__half_as_ushort(h1) << 16);
}

__device__ __forceinline__ float warpSum(float v) {
    #pragma unroll
    for (int o = 16; o; o >>= 1) v += __shfl_xor_sync(0xffffffffu, v, o);
    return v;
}
__device__ __forceinline__ float blockSum(float v) {
    __shared__ float sm[8];
    int lane = threadIdx.x & 31, w = threadIdx.x >> 5;
    v = warpSum(v);
    __syncthreads();
    if (lane == 0) sm[w] = v;
    __syncthreads();
    float r = 0.f;
    #pragma unroll
    for (int i = 0; i < 8; i++) r += sm[i];
    return r;
}

// ---------------- f32 -> fp16 hi plane (8 words / 32B out per thread) ----------------
__global__ void split_hi_k(const float* __restrict__ in, uint32_t* __restrict__ hi, int nWords) {
    int i = (blockIdx.x * 256 + threadIdx.x) * 8;
    if (i < nWords) {
        #pragma unroll
        for (int j = 0; j < 2; j++) {
            float4 a = *(const float4*)(in + 2 * (size_t)(i + j * 4));
            float4 b = *(const float4*)(in + 2 * (size_t)(i + j * 4) + 4);
            uint4 o;
            o.x = pack_hi(a.x, a.y); o.y = pack_hi(a.z, a.w);
            o.z = pack_hi(b.x, b.y); o.w = pack_hi(b.z, b.w);
            *(uint4*)(hi + i + j * 4) = o;
        }
    }
}

// ---------------- embed + input layernorm -> f32 x ----------------
__global__ void embed_ln_k(const int* __restrict__ src, const float* __restrict__ emb,
                           const float* __restrict__ s, const float* __restrict__ b,
                           float* __restrict__ out) {
    int row = blockIdx.x, t = threadIdx.x;
    int tok = src[row];
    const float SC = 22.62741699796952f;
    float v0 = emb[(size_t)tok * E_DIM + t]       * SC;
    float v1 = emb[(size_t)tok * E_DIM + t + 256] * SC;
    float mean = blockSum(v0 + v1) * (1.f / E_DIM);
    float d0 = v0 - mean, d1 = v1 - mean;
    float var = blockSum(d0 * d0 + d1 * d1) * (1.f / E_DIM);
    float r = rsqrtf(var + 1e-5f);
    out[(size_t)row * E_DIM + t]       = d0 * r * s[t]       + b[t];
    out[(size_t)row * E_DIM + t + 256] = d1 * r * s[t + 256] + b[t + 256];
}

// ---------------- layernorm f32 -> split planes ----------------
__global__ void layernorm_split_k(const float* __restrict__ in, const float* __restrict__ s,
                                  const float* __restrict__ b,
                                  uint32_t* __restrict__ oh, uint32_t* __restrict__ ol) {
    int row = blockIdx.x, t = threadIdx.x;
    float2 v = *(const float2*)(in + (size_t)row * E_DIM + 2 * t);
    float mean = blockSum(v.x + v.y) * (1.f / E_DIM);
    float d0 = v.x - mean, d1 = v.y - mean;
    float var = blockSum(d0 * d0 + d1 * d1) * (1.f / E_DIM);
    float r = rsqrtf(var + 1e-5f);
    float y0 = d0 * r * s[2 * t]     + b[2 * t];
    float y1 = d1 * r * s[2 * t + 1] + b[2 * t + 1];
    uint32_t h, l;
    splitpack(y0, y1, h, l);
    oh[(size_t)row * 256 + t] = h;
    ol[(size_t)row * 256 + t] = l;
}

// ---------------- mma / ldmatrix / cp.async primitives ----------------
#define MMA_F16(C, A0, A1, A2, A3, B0, B1)                                      \
    asm volatile("mma.sync.aligned.m16n8k16.row.col.f32.f16.f16.f32 "           \
                 "{%0,%1,%2,%3},{%4,%5,%6,%7},{%8,%9},{%0,%1,%2,%3};"           \
                 : "+f"(C[0]), "+f"(C[1]), "+f"(C[2]), "+f"(C[3])               \
                 : "r"(A0), "r"(A1), "r"(A2), "r"(A3), "r"(B0), "r"(B1))

__device__ __forceinline__ void ldsm4(uint32_t& r0, uint32_t& r1, uint32_t& r2, uint32_t& r3,
                                      uint32_t addr) {
    asm volatile("ldmatrix.sync.aligned.m8n8.x4.shared.b16 {%0,%1,%2,%3}, [%4];"
                 : "=r"(r0), "=r"(r1), "=r"(r2), "=r"(r3) : "r"(addr));
}

__device__ __forceinline__ void cp16w(uint32_t* dst, const uint32_t* src, bool pred) {
    uint32_t d = (uint32_t)__cvta_generic_to_shared(dst);
    int sz = pred ? 16 : 0;
    asm volatile("cp.async.cg.shared.global [%0], [%1], 16, %2;"
                 :: "r"(d), "l"(src), "r"(sz));
}

// ---------------- fused attention: scores + rel-bias gather + mask + softmax -> probs ----
// grid (2 row-tiles, 32 bh), 256 threads. K staged whole (K-dim = 64).
#define ATT_STRIDE 36
#define ATT_SMEM ((128 * ATT_STRIDE + 256 * ATT_STRIDE) * 4 + 128 * 4 * 4)  // 57344
__global__ __launch_bounds__(256, 1)
void attn_k(const uint32_t* __restrict__ qkvH, const float* __restrict__ qr,
            uint32_t* __restrict__ ph) {
    extern __shared__ uint32_t asm_[];
    uint32_t* qs = asm_;
    uint32_t* ks = asm_ + 128 * ATT_STRIDE;
    float* red = (float*)(ks + 256 * ATT_STRIDE);   // [128][4]

    int tile = blockIdx.x;
    int bh = blockIdx.y;
    int zb = bh >> 3, zh = bh & 7;
    const uint32_t* Q = qkvH + (size_t)zb * (256 * 768) + zh * 32;
    const uint32_t* K = Q + 256;
    const float* qrb = qr + (size_t)bh * (256 * 512);
    int l0 = tile * 128;

    int tid = threadIdx.x, lane = tid & 31, wid = tid >> 5;

    // stage Q (128 rows x 32 words) and K (256 rows x 32 words)
    {
        int lrow = tid >> 1, seg = (tid & 1) * 16;
        const uint32_t* qrow = Q + (size_t)(l0 + lrow) * 768 + seg;
        uint32_t* qd = qs + lrow * ATT_STRIDE + seg;
        #pragma unroll
        for (int j = 0; j < 4; j++) cp16w(qd + j * 4, qrow + j * 4, true);
        const uint32_t* krow = K + (size_t)tid * 768;
        uint32_t* kd = ks + tid * ATT_STRIDE;
        #pragma unroll
        for (int j = 0; j < 8; j++) cp16w(kd + j * 4, krow + j * 4, true);
    }
    asm volatile("cp.async.commit_group;");
    asm volatile("cp.async.wait_group 0;");
    __syncthreads();

    int warpM = wid >> 2, warpN = wid & 3;
    int wm0 = warpM * 64, wn0 = warpN * 64;
    int g = lane >> 2, tg = lane & 3;
    uint32_t smQ = (uint32_t)__cvta_generic_to_shared(qs);
    uint32_t smK = (uint32_t)__cvta_generic_to_shared(ks);
    uint32_t a_base = smQ + ((uint32_t)(wm0 + (lane & 15)) * ATT_STRIDE + ((lane & 16) ? 4 : 0)) * 4;
    uint32_t b_base = smK + ((uint32_t)(wn0 + (lane & 7) + ((lane & 16) ? 8 : 0)) * ATT_STRIDE
                             + ((lane & 8) ? 4 : 0)) * 4;

    float acc[4][8][4] = {};
    #pragma unroll
    for (int c = 0; c < 4; c++) {
        uint32_t koff = (uint32_t)c * 32;     // 8 words = 32 bytes per k16 chunk
        uint32_t Bf[8][2];
        #pragma unroll
        for (int t = 0; t < 4; t++)
            ldsm4(Bf[2 * t][0], Bf[2 * t][1], Bf[2 * t + 1][0], Bf[2 * t + 1][1],
                  b_base + koff + (uint32_t)t * 16 * ATT_STRIDE * 4);
        #pragma unroll
        for (int mi = 0; mi < 4; mi++) {
            uint32_t Af[4];
            ldsm4(Af[0], Af[1], Af[2], Af[3],
                  a_base + koff + (uint32_t)mi * 16 * ATT_STRIDE * 4);
            #pragma unroll
            for (int ni = 0; ni < 8; ni++)
                MMA_F16(acc[mi][ni], Af[0], Af[1], Af[2], Af[3], Bf[ni][0], Bf[ni][1]);
        }
    }
    __syncthreads();   // smem reuse (red overlaps nothing, but order writes)

    // scale + rel-bias gather + bool-mask
    #pragma unroll
    for (int mi = 0; mi < 4; mi++) {
        #pragma unroll
        for (int rr = 0; rr < 2; rr++) {
            int lrow = wm0 + mi * 16 + g + rr * 8;
            int lglob = l0 + lrow;
            const float* qrl = qrb + (size_t)lglob * 512 + (255 - lglob);
            #pragma unroll
            for (int ni = 0; ni < 8; ni++) {
                int m = wn0 + ni * 8 + tg * 2;
                float b0 = qrl[m], b1 = qrl[m + 1];
                acc[mi][ni][rr * 2]     = acc[mi][ni][rr * 2]     * 0.125f + b0 + ((m     > lglob) ? 1.f : 0.f);
                acc[mi][ni][rr * 2 + 1] = acc[mi][ni][rr * 2 + 1] * 0.125f + b1 + ((m + 1 > lglob) ? 1.f : 0.f);
            }
        }
    }

    // row max (quad shfl -> cross-warp smem)
    float rmax[4][2];
    #pragma unroll
    for (int mi = 0; mi < 4; mi++)
        #pragma unroll
        for (int rr = 0; rr < 2; rr++) {
            float mx = -3.4e38f;
            #pragma unroll
            for (int ni = 0; ni < 8; ni++) {
                mx = fmaxf(mx, acc[mi][ni][rr * 2]);
                mx = fmaxf(mx, acc[mi][ni][rr * 2 + 1]);
            }
            mx = fmaxf(mx, __shfl_xor_sync(0xffffffffu, mx, 1));
            mx = fmaxf(mx, __shfl_xor_sync(0xffffffffu, mx, 2));
            int lrow = wm0 + mi * 16 + g + rr * 8;
            if (tg == 0) red[lrow * 4 + warpN] = mx;
            rmax[mi][rr] = 0.f;  // placeholder
        }
    __syncthreads();
    #pragma unroll
    for (int mi = 0; mi < 4; mi++)
        #pragma unroll
        for (int rr = 0; rr < 2; rr++) {
            int lrow = wm0 + mi * 16 + g + rr * 8;
            float mx = fmaxf(fmaxf(red[lrow * 4 + 0], red[lrow * 4 + 1]),
                             fmaxf(red[lrow * 4 + 2], red[lrow * 4 + 3]));
            rmax[mi][rr] = mx;
        }
    __syncthreads();

    // exp + row sum
    float rsum[4][2];
    #pragma unroll
    for (int mi = 0; mi < 4; mi++)
        #pragma unroll
        for (int rr = 0; rr < 2; rr++) {
            float s = 0.f;
            #pragma unroll
            for (int ni = 0; ni < 8; ni++) {
                float e0 = expf(acc[mi][ni][rr * 2]     - rmax[mi][rr]);
                float e1 = expf(acc[mi][ni][rr * 2 + 1] - rmax[mi][rr]);
                acc[mi][ni][rr * 2] = e0; acc[mi][ni][rr * 2 + 1] = e1;
                s += e0 + e1;
            }
            s += __shfl_xor_sync(0xffffffffu, s, 1);
            s += __shfl_xor_sync(0xffffffffu, s, 2);
            int lrow = wm0 + mi * 16 + g + rr * 8;
            if (tg == 0) red[lrow * 4 + warpN] = s;
            rsum[mi][rr] = 0.f;
        }
    __syncthreads();
    #pragma unroll
    for (int mi = 0; mi < 4; mi++)
        #pragma unroll
        for (int rr = 0; rr < 2; rr++) {
            int lrow = wm0 + mi * 16 + g + rr * 8;
            rsum[mi][rr] = red[lrow * 4 + 0] + red[lrow * 4 + 1]
                         + red[lrow * 4 + 2] + red[lrow * 4 + 3];
        }

    // write probs hi plane
    uint32_t* pb = ph + (size_t)bh * (S_LEN * 128);
    #pragma unroll
    for (int mi = 0; mi < 4; mi++)
        #pragma unroll
        for (int rr = 0; rr < 2; rr++) {
            int lglob = l0 + wm0 + mi * 16 + g + rr * 8;
            float inv = 1.f / rsum[mi][rr];
            #pragma unroll
            for (int ni = 0; ni < 8; ni++) {
                float p0 = acc[mi][ni][rr * 2] * inv;
                float p1 = acc[mi][ni][rr * 2 + 1] * inv;
                pb[(size_t)lglob * 128 + (wn0 >> 1) + ni * 4 + tg] = pack_hi(p0, p1);
            }
        }
}

// ---------------- V transpose: qkv hi plane -> vT[bh][64 d][128 s-words] ----------------
__global__ void vtrans_k(const uint32_t* __restrict__ qkvH, uint32_t* __restrict__ vT) {
    __shared__ uint32_t vs[256][33];
    int bh = blockIdx.x;
    int zb = bh >> 3, zh = bh & 7;
    const uint32_t* V = qkvH + (size_t)zb * (256 * 768) + 512 + zh * 32;
    int tid = threadIdx.x;
    #pragma unroll
    for (int j = 0; j < 32; j++) {
        int idx = tid + j * 256;
        int row = idx >> 5, w = idx & 31;
        vs[row][w] = V[(size_t)row * 768 + w];
    }
    __syncthreads();
    uint32_t* o = vT + (size_t)bh * 8192;
    #pragma unroll
    for (int j = 0; j < 32; j++) {
        int idx = tid + j * 256;
        int d = idx >> 7, sw = idx & 127;
        uint32_t w0 = vs[2 * sw][d >> 1], w1 = vs[2 * sw + 1][d >> 1];
        int sh = (d & 1) * 16;
        o[idx] = ((w0 >> sh) & 0xffffu) | (((w1 >> sh) & 0xffffu) << 16);
    }
}

// smem geometry
#define PLANE_W   (128 * 12)
#define PLANE_B   (PLANE_W * 4)
#define STAGES    3
#define SMEM3     (STAGES * 3 * PLANE_B)
#define SMEM2     (STAGES * 2 * PLANE_B)

// ---------------- fp16 GEMM, 128x128 CTA tile, chunk k=16 (8 words) ----------------
// ALO=1: A hi+lo (2-term); ALO=0: hi only. B: hi plane only.
// EPI: 0 = f32 out (+bias); 1 = f32 splitK atomicAdd (+bias at sk==0);
//      2 = planes out bias+GELU; 3 = planes out (+bias, Cl optional).
template<int EPI, int NSPLIT, int ALO>
__global__ __launch_bounds__(256, 2)
void bgemm(const uint32_t* __restrict__ Ah, const uint32_t* __restrict__ Al,
           const uint32_t* __restrict__ Bh,
           const float* __restrict__ bias,
           float* __restrict__ Cf, uint32_t* __restrict__ Ch, uint32_t* __restrict__ Cl,
           int M, int N, int Kw, int ldaw, int ldbw, int ldc,
           int aOffB, int aOffH, int bOffB, int bOffH, int cOffB, int cOffH) {
    extern __shared__ uint32_t smu[];
    constexpr int NPL   = 2 + ALO;
    constexpr int STW   = NPL * PLANE_W;
    constexpr int STB   = NPL * PLANE_B;
    constexpr int BOFFW = (1 + ALO) * PLANE_W;
    constexpr int BOFFB = (1 + ALO) * PLANE_B;

    int z = blockIdx.z;
    int sk = z % NSPLIT;
    int zz = z / NSPLIT;
    int zb = zz >> 3, zh = zz & 7;
    Ah += (size_t)zb * aOffB + (size_t)zh * aOffH;
    if (ALO) Al += (size_t)zb * aOffB + (size_t)zh * aOffH;
    Bh += (size_t)zb * bOffB + (size_t)zh * bOffH;
    size_t cAdj = (size_t)zb * cOffB + (size_t)zh * cOffH;
    if (EPI <= 1) Cf += cAdj; else { Ch += cAdj; if (Cl) Cl += cAdj; }

    int kLenW = Kw / NSPLIT;
    int kw0   = sk * kLenW;
    int nk    = kLenW >> 3;

    int tid  = threadIdx.x;
    int lane = tid & 31, wid = tid >> 5;
    int wm0 = (wid >> 2) * 64;
    int wn0 = (wid & 3) * 32;
    int g   = lane >> 2;
    int tg  = lane & 3;
    int row0 = blockIdx.y * 128, col0 = blockIdx.x * 128;

    int lrow = tid >> 1;
    int seg  = (tid & 1) * 4;

    uint32_t smBase = (uint32_t)__cvta_generic_to_shared(smu);
    uint32_t a_off = ((uint32_t)(wm0 + (lane & 15)) * 12 + ((lane & 16) ? 4 : 0)) * 4;
    uint32_t b_off = ((uint32_t)(wn0 + (lane & 7) + ((lane & 16) ? 8 : 0)) * 12
                      + ((lane & 8) ? 4 : 0)) * 4;

    float acc[4][4][4] = {};

    auto COMPUTE = [&](int buf) {
        uint32_t sb = smBase + (uint32_t)buf * STB;
        uint32_t aH = sb + a_off;
        uint32_t aL = aH + PLANE_B;
        uint32_t bH = sb + BOFFB + b_off;
        uint32_t Bhf[4][2];
        ldsm4(Bhf[0][0], Bhf[0][1], Bhf[1][0], Bhf[1][1], bH);
        ldsm4(Bhf[2][0], Bhf[2][1], Bhf[3][0], Bhf[3][1], bH + 16 * 12 * 4);
        #pragma unroll
        for (int mi = 0; mi < 4; mi++) {
            uint32_t Af[4];
            ldsm4(Af[0], Af[1], Af[2], Af[3], aH + (uint32_t)mi * 16 * 12 * 4);
            uint32_t Lf[4];
            if (ALO) ldsm4(Lf[0], Lf[1], Lf[2], Lf[3], aL + (uint32_t)mi * 16 * 12 * 4);
            #pragma unroll
            for (int ni = 0; ni < 4; ni++) {
                MMA_F16(acc[mi][ni], Af[0], Af[1], Af[2], Af[3], Bhf[ni][0], Bhf[ni][1]);
                if (ALO)
                    MMA_F16(acc[mi][ni], Lf[0], Lf[1], Lf[2], Lf[3], Bhf[ni][0], Bhf[ni][1]);
            }
        }
    };

    auto LOADNT = [&](int chunk, int buf) {
        int kws = kw0 + (chunk << 3) + seg;
        uint32_t* st = smu + buf * STW;
        cp16w(st + lrow * 12 + seg, Ah + (size_t)(row0 + lrow) * ldaw + kws, true);
        if (ALO)
            cp16w(st + PLANE_W + lrow * 12 + seg, Al + (size_t)(row0 + lrow) * ldaw + kws, true);
        bool p = (col0 + lrow) < N;
        cp16w(st + BOFFW + lrow * 12 + seg, Bh + (size_t)(col0 + lrow) * ldbw + kws, p);
    };
    int pre = (nk < STAGES - 1) ? nk : (STAGES - 1);
    for (int s = 0; s < pre; s++) {
        LOADNT(s, s);
        asm volatile("cp.async.commit_group;");
    }
    for (int i = 0; i < nk; i++) {
        int buf = i % STAGES;
        asm volatile("cp.async.wait_group %0;" :: "n"(STAGES - 2));
        __syncthreads();
        COMPUTE(buf);
        int nxt = i + STAGES - 1;
        if (nxt < nk) LOADNT(nxt, nxt % STAGES);
        asm volatile("cp.async.commit_group;");
    }

    // ---------------- epilogue ----------------
    #pragma unroll
    for (int mi = 0; mi < 4; mi++) {
        #pragma unroll
        for (int rr = 0; rr < 2; rr++) {
            int r = row0 + wm0 + mi * 16 + g + rr * 8;
            #pragma unroll
            for (int ni = 0; ni < 4; ni++) {
                int c = col0 + wn0 + ni * 8 + tg * 2;
                float v0 = acc[mi][ni][rr * 2];
                float v1 = acc[mi][ni][rr * 2 + 1];
                if (EPI == 0 && NSPLIT == 1) {
                    float* Crow = Cf + (size_t)r * ldc;
                    if (c + 1 < N) {
                        if (bias) { v0 += bias[c]; v1 += bias[c + 1]; }
                        *(float2*)&Crow[c] = make_float2(v0, v1);
                    } else if (c < N) {
                        if (bias) v0 += bias[c];
                        Crow[c] = v0;
                    }
                } else if (EPI == 1) {
                    float* Crow = Cf + (size_t)r * ldc;
                    if (bias && sk == 0) {
                        if (c < N)     v0 += bias[c];
                        if (c + 1 < N) v1 += bias[c + 1];
                    }
                    if (c < N)     atomicAdd(&Crow[c], v0);
                    if (c + 1 < N) atomicAdd(&Crow[c + 1], v1);
                } else if (EPI >= 2) {
                    if (c < N) {
                        if (bias) { v0 += bias[c]; v1 += bias[c + 1]; }
                        if (EPI == 2) {
                            v0 = 0.5f * v0 * (1.f + erff(v0 * 0.7071067811865476f));
                            v1 = 0.5f * v1 * (1.f + erff(v1 * 0.7071067811865476f));
                        }
                        uint32_t h, l;
                        splitpack(v0, v1, h, l);
                        size_t idx = (size_t)r * ldc + (c >> 1);
                        Ch[idx] = h;
                        if (Cl) Cl[idx] = l;
                    }
                }
            }
        }
    }
}

// ---------------- driver ----------------
extern "C" void kernel_launch(void* const* d_in, const int* in_sizes, int n_in,
                              void* d_out, int out_size) {
    const int*   src   = (const int*)  d_in[0];
    const float* emb   = (const float*)d_in[1];
    const float* rel   = (const float*)d_in[2];
    const float* nin_s = (const float*)d_in[3];
    const float* nin_b = (const float*)d_in[4];
    const float* inW   = (const float*)d_in[5];
    const float* inB   = (const float*)d_in[6];
    const float* outW  = (const float*)d_in[7];
    const float* outB  = (const float*)d_in[8];
    const float* ln1s  = (const float*)d_in[9];
    const float* ln1b  = (const float*)d_in[10];
    const float* ln2s  = (const float*)d_in[11];
    const float* ln2b  = (const float*)d_in[12];
    const float* w1    = (const float*)d_in[13];
    const float* b1    = (const float*)d_in[14];
    const float* w2    = (const float*)d_in[15];
    const float* b2    = (const float*)d_in[16];
    const float* nfs   = (const float*)d_in[17];
    const float* nfb   = (const float*)d_in[18];
    const float* decW  = (const float*)d_in[19];
    const float* decB  = (const float*)d_in[20];
    float* out = (float*)d_out;

    float *x, *qr;
    cudaGetSymbolAddress((void**)&x,  g_x);
    cudaGetSymbolAddress((void**)&qr, g_qr);
    uint32_t *hH,*hL,*qkvH,*prH,*vT,*oH,*oL,*gH,*gL;
    uint32_t *WiH,*WoH,*W1H,*W2H,*WdH,*relH;
    cudaGetSymbolAddress((void**)&hH,   p_h_hi);   cudaGetSymbolAddress((void**)&hL,   p_h_lo);
    cudaGetSymbolAddress((void**)&qkvH, p_qkv_hi);
    cudaGetSymbolAddress((void**)&prH,  p_pr_hi);
    cudaGetSymbolAddress((void**)&vT,   p_vT);
    cudaGetSymbolAddress((void**)&oH,   p_o_hi);   cudaGetSymbolAddress((void**)&oL,   p_o_lo);
    cudaGetSymbolAddress((void**)&gH,   p_g_hi);   cudaGetSymbolAddress((void**)&gL,   p_g_lo);
    cudaGetSymbolAddress((void**)&WiH,  p_Wi_hi);
    cudaGetSymbolAddress((void**)&WoH,  p_Wo_hi);
    cudaGetSymbolAddress((void**)&W1H,  p_W1_hi);
    cudaGetSymbolAddress((void**)&W2H,  p_W2_hi);
    cudaGetSymbolAddress((void**)&WdH,  p_Wd_hi);
    cudaGetSymbolAddress((void**)&relH, p_rel_hi);

    cudaFuncSetAttribute(bgemm<3,1,1>, cudaFuncAttributeMaxDynamicSharedMemorySize, SMEM3);
    cudaFuncSetAttribute(bgemm<0,1,0>, cudaFuncAttributeMaxDynamicSharedMemorySize, SMEM2);
    cudaFuncSetAttribute(bgemm<3,1,0>, cudaFuncAttributeMaxDynamicSharedMemorySize, SMEM2);
    cudaFuncSetAttribute(bgemm<1,4,1>, cudaFuncAttributeMaxDynamicSharedMemorySize, SMEM3);
    cudaFuncSetAttribute(bgemm<2,1,1>, cudaFuncAttributeMaxDynamicSharedMemorySize, SMEM3);
    cudaFuncSetAttribute(attn_k,       cudaFuncAttributeMaxDynamicSharedMemorySize, ATT_SMEM);

    // weight splits (hi-only, 8 words/thread)
    split_hi_k<<<(4*1536*256/8 + 255)/256, 256>>>(inW,  WiH, 4*1536*256);
    split_hi_k<<<(4*512*256/8  + 255)/256, 256>>>(outW, WoH, 4*512*256);
    split_hi_k<<<(4*2048*256/8 + 255)/256, 256>>>(w1,   W1H, 4*2048*256);
    split_hi_k<<<(4*512*1024/8 + 255)/256, 256>>>(w2,   W2H, 4*512*1024);
    split_hi_k<<<(V_DIM*256/8  + 255)/256, 256>>>(decW, WdH, V_DIM*256);
    split_hi_k<<<(511*256/8    + 255)/256, 256>>>(rel,  relH, 511*256);

    embed_ln_k<<<N_ROWS, 256>>>(src, emb, nin_s, nin_b, x);

    for (int l = 0; l < 4; l++) {
        const uint32_t* WiHl = WiH + (size_t)l * 1536 * 256;
        const uint32_t* WoHl = WoH + (size_t)l * 512 * 256;
        const uint32_t* W1Hl = W1H + (size_t)l * 2048 * 256;
        const uint32_t* W2Hl = W2H + (size_t)l * 512 * 1024;
        const float* inB_l  = inB  + (size_t)l * QKV_DIM;
        const float* outB_l = outB + (size_t)l * E_DIM;
        const float* b1_l   = b1   + (size_t)l * FF_DIM;
        const float* b2_l   = b2   + (size_t)l * E_DIM;

        layernorm_split_k<<<N_ROWS, 256>>>(x, ln1s + l*E_DIM, ln1b + l*E_DIM, hH, hL);

        // qkv hi plane = h @ inW^T + inB   (2-term A)
        bgemm<3,1,1><<<dim3(12, 8, 1), 256, SMEM3>>>(hH, hL, WiHl, inB_l,
            (float*)0, qkvH, (uint32_t*)0, N_ROWS, QKV_DIM, 256, 256, 256, 768,
            0,0, 0,0, 0,0);

        // V transpose for NT PV
        vtrans_k<<<N_BH, 256>>>(qkvH, vT);

        // qr f32 = Q @ rel^T  (1-term)
        bgemm<0,1,0><<<dim3(4, 2, N_BH), 256, SMEM2>>>(qkvH, (const uint32_t*)0, relH,
            (const float*)0, qr, (uint32_t*)0, (uint32_t*)0,
            S_LEN, 511, 32, 768, 256, 512,
            256*768, 32, 0, 32, 8*131072, 131072);

        // fused scores + bias + mask + softmax -> probs hi plane
        attn_k<<<dim3(2, N_BH), 256, ATT_SMEM>>>(qkvH, qr, prH);

        // o planes = probs @ V^T   (NT, pipelined, 1-term)
        bgemm<3,1,0><<<dim3(1, 2, N_BH), 256, SMEM2>>>(prH, (const uint32_t*)0, vT,
            (const float*)0, (float*)0, oH, oL,
            S_LEN, 64, 128, 128, 128, 256,
            8*32768, 32768, 8*8192, 8192, 65536, 32);

        // x += o @ outW^T + outB   (splitK 4, 2-term A)
        bgemm<1,4,1><<<dim3(4, 8, 4), 256, SMEM3>>>(oH, oL, WoHl, outB_l,
            x, (uint32_t*)0, (uint32_t*)0, N_ROWS, E_DIM, 256, 256, 256, E_DIM,
            0,0, 0,0, 0,0);

        layernorm_split_k<<<N_ROWS, 256>>>(x, ln2s + l*E_DIM, ln2b + l*E_DIM, hH, hL);

        // g planes = gelu(h @ w1^T + b1)  (2-term A)
        bgemm<2,1,1><<<dim3(16, 8, 1), 256, SMEM3>>>(hH, hL, W1Hl, b1_l,
            (float*)0, gH, gL, N_ROWS, FF_DIM, 256, 256, 256, 1024,
            0,0, 0,0, 0,0);

        // x += g @ w2^T + b2   (splitK 4, 2-term A)
        bgemm<1,4,1><<<dim3(4, 8, 4), 256, SMEM3>>>(gH, gL, W2Hl, b2_l,
            x, (uint32_t*)0, (uint32_t*)0, N_ROWS, E_DIM, 1024, 1024, 1024, E_DIM,
            0,0, 0,0, 0,0);
    }

    layernorm_split_k<<<N_ROWS, 256>>>(x, nfs, nfb, hH, hL);

    // out f32 = h @ dec_w^T + dec_b   (1-term)
    bgemm<0,1,0><<<dim3(250, 8, 1), 256, SMEM2>>>(hH, (const uint32_t*)0, WdH, decB,
        out, (uint32_t*)0, (uint32_t*)0, N_ROWS, V_DIM, 256, 256, 256, V_DIM,
        0,0, 0,0, 0,0);
}

// round 10
// speedup vs baseline: 3.1734x; 1.0001x over previous
#include <cuda_runtime.h>
#include <cuda_fp16.h>
#include <math.h>
#include <stdint.h>

// ---------------- problem constants ----------------
#define N_ROWS   1024
#define E_DIM    512
#define QKV_DIM  1536
#define FF_DIM   2048
#define V_DIM    32000
#define N_BH     32
#define S_LEN    256

// ---------------- f32 scratch ----------------
__device__ float g_x [N_ROWS * E_DIM];
__device__ float g_qr[N_BH * S_LEN * 512];

// ---------------- packed fp16 planes (word = 2 consecutive-k halves) ----------------
__device__ uint32_t p_h_hi  [N_ROWS * 256],  p_h_lo  [N_ROWS * 256];
__device__ uint32_t p_qkv_hi[N_ROWS * 768];
__device__ uint32_t p_pr_hi [N_BH * S_LEN * 128];
__device__ uint32_t p_vT    [N_BH * 64 * 128];
__device__ uint32_t p_o_hi  [N_ROWS * 256],  p_o_lo  [N_ROWS * 256];
__device__ uint32_t p_g_hi  [N_ROWS * 1024], p_g_lo  [N_ROWS * 1024];
__device__ uint32_t p_Wi_hi [4 * 1536 * 256];
__device__ uint32_t p_Wo_hi [4 * 512 * 256];
__device__ uint32_t p_W1_hi [4 * 2048 * 256];
__device__ uint32_t p_W2_hi [4 * 512 * 1024];
__device__ uint32_t p_Wd_hi [V_DIM * 256];
__device__ uint32_t p_rel_hi[511 * 256];

// ---------------- helpers ----------------
__device__ __forceinline__ void splitpack(float v0, float v1, uint32_t& hi, uint32_t& lo) {
    __half h0 = __float2half_rn(v0);
    __half h1 = __float2half_rn(v1);
    float r0 = v0 - __half2float(h0);
    float r1 = v1 - __half2float(h1);
    __half l0 = __float2half_rn(r0);
    __half l1 = __float2half_rn(r1);
    hi = (uint32_t)__half_as_ushort(h0) | ((uint32_t)__half_as_ushort(h1) << 16);
    lo = (uint32_t)__half_as_ushort(l0) | ((uint32_t)__half_as_ushort(l1) << 16);
}
__device__ __forceinline__ uint32_t pack_hi(float v0, float v1) {
    __half h0 = __float2half_rn(v0);
    __half h1 = __float2half_rn(v1);
    return (uint32_t)__half_as_ushort(h0) | ((uint32_t)__half_as_ushort(h1) << 16);
}

__device__ __forceinline__ float warpSum(float v) {
    #pragma unroll
    for (int o = 16; o; o >>= 1) v += __shfl_xor_sync(0xffffffffu, v, o);
    return v;
}
__device__ __forceinline__ float blockSum(float v) {
    __shared__ float sm[8];
    int lane = threadIdx.x & 31, w = threadIdx.x >> 5;
    v = warpSum(v);
    __syncthreads();
    if (lane == 0) sm[w] = v;
    __syncthreads();
    float r = 0.f;
    #pragma unroll
    for (int i = 0; i < 8; i++) r += sm[i];
    return r;
}

// ---------------- f32 -> fp16 hi plane (8 words / 32B out per thread) ----------------
__global__ void split_hi_k(const float* __restrict__ in, uint32_t* __restrict__ hi, int nWords) {
    int i = (blockIdx.x * 256 + threadIdx.x) * 8;
    if (i < nWords) {
        #pragma unroll
        for (int j = 0; j < 2; j++) {
            float4 a = *(const float4*)(in + 2 * (size_t)(i + j * 4));
            float4 b = *(const float4*)(in + 2 * (size_t)(i + j * 4) + 4);
            uint4 o;
            o.x = pack_hi(a.x, a.y); o.y = pack_hi(a.z, a.w);
            o.z = pack_hi(b.x, b.y); o.w = pack_hi(b.z, b.w);
            *(uint4*)(hi + i + j * 4) = o;
        }
    }
}

// ---------------- embed + input layernorm -> f32 x ----------------
__global__ void embed_ln_k(const int* __restrict__ src, const float* __restrict__ emb,
                           const float* __restrict__ s, const float* __restrict__ b,
                           float* __restrict__ out) {
    int row = blockIdx.x, t = threadIdx.x;
    int tok = src[row];
    const float SC = 22.62741699796952f;
    float v0 = emb[(size_t)tok * E_DIM + t]       * SC;
    float v1 = emb[(size_t)tok * E_DIM + t + 256] * SC;
    float mean = blockSum(v0 + v1) * (1.f / E_DIM);
    float d0 = v0 - mean, d1 = v1 - mean;
    float var = blockSum(d0 * d0 + d1 * d1) * (1.f / E_DIM);
    float r = rsqrtf(var + 1e-5f);
    out[(size_t)row * E_DIM + t]       = d0 * r * s[t]       + b[t];
    out[(size_t)row * E_DIM + t + 256] = d1 * r * s[t + 256] + b[t + 256];
}

// ---------------- layernorm f32 -> split planes ----------------
__global__ void layernorm_split_k(const float* __restrict__ in, const float* __restrict__ s,
                                  const float* __restrict__ b,
                                  uint32_t* __restrict__ oh, uint32_t* __restrict__ ol) {
    int row = blockIdx.x, t = threadIdx.x;
    float2 v = *(const float2*)(in + (size_t)row * E_DIM + 2 * t);
    float mean = blockSum(v.x + v.y) * (1.f / E_DIM);
    float d0 = v.x - mean, d1 = v.y - mean;
    float var = blockSum(d0 * d0 + d1 * d1) * (1.f / E_DIM);
    float r = rsqrtf(var + 1e-5f);
    float y0 = d0 * r * s[2 * t]     + b[2 * t];
    float y1 = d1 * r * s[2 * t + 1] + b[2 * t + 1];
    uint32_t h, l;
    splitpack(y0, y1, h, l);
    oh[(size_t)row * 256 + t] = h;
    ol[(size_t)row * 256 + t] = l;
}

// ---------------- mma / ldmatrix / cp.async primitives ----------------
#define MMA_F16(C, A0, A1, A2, A3, B0, B1)                                      \
    asm volatile("mma.sync.aligned.m16n8k16.row.col.f32.f16.f16.f32 "           \
                 "{%0,%1,%2,%3},{%4,%5,%6,%7},{%8,%9},{%0,%1,%2,%3};"           \
                 : "+f"(C[0]), "+f"(C[1]), "+f"(C[2]), "+f"(C[3])               \
                 : "r"(A0), "r"(A1), "r"(A2), "r"(A3), "r"(B0), "r"(B1))

__device__ __forceinline__ void ldsm4(uint32_t& r0, uint32_t& r1, uint32_t& r2, uint32_t& r3,
                                      uint32_t addr) {
    asm volatile("ldmatrix.sync.aligned.m8n8.x4.shared.b16 {%0,%1,%2,%3}, [%4];"
                 : "=r"(r0), "=r"(r1), "=r"(r2), "=r"(r3) : "r"(addr));
}

__device__ __forceinline__ void cp16w(uint32_t* dst, const uint32_t* src, bool pred) {
    uint32_t d = (uint32_t)__cvta_generic_to_shared(dst);
    int sz = pred ? 16 : 0;
    asm volatile("cp.async.cg.shared.global [%0], [%1], 16, %2;"
                 :: "r"(d), "l"(src), "r"(sz));
}

// ---------------- fused attention: scores + rel-bias gather + mask + softmax -> probs ----
#define ATT_STRIDE 36
#define ATT_SMEM ((128 * ATT_STRIDE + 256 * ATT_STRIDE) * 4 + 128 * 4 * 4)
__global__ __launch_bounds__(256, 1)
void attn_k(const uint32_t* __restrict__ qkvH, const float* __restrict__ qr,
            uint32_t* __restrict__ ph) {
    extern __shared__ uint32_t asm_[];
    uint32_t* qs = asm_;
    uint32_t* ks = asm_ + 128 * ATT_STRIDE;
    float* red = (float*)(ks + 256 * ATT_STRIDE);

    int tile = blockIdx.x;
    int bh = blockIdx.y;
    int zb = bh >> 3, zh = bh & 7;
    const uint32_t* Q = qkvH + (size_t)zb * (256 * 768) + zh * 32;
    const uint32_t* K = Q + 256;
    const float* qrb = qr + (size_t)bh * (256 * 512);
    int l0 = tile * 128;

    int tid = threadIdx.x, lane = tid & 31, wid = tid >> 5;

    {
        int lrow = tid >> 1, seg = (tid & 1) * 16;
        const uint32_t* qrow = Q + (size_t)(l0 + lrow) * 768 + seg;
        uint32_t* qd = qs + lrow * ATT_STRIDE + seg;
        #pragma unroll
        for (int j = 0; j < 4; j++) cp16w(qd + j * 4, qrow + j * 4, true);
        const uint32_t* krow = K + (size_t)tid * 768;
        uint32_t* kd = ks + tid * ATT_STRIDE;
        #pragma unroll
        for (int j = 0; j < 8; j++) cp16w(kd + j * 4, krow + j * 4, true);
    }
    asm volatile("cp.async.commit_group;");
    asm volatile("cp.async.wait_group 0;");
    __syncthreads();

    int warpM = wid >> 2, warpN = wid & 3;
    int wm0 = warpM * 64, wn0 = warpN * 64;
    int g = lane >> 2, tg = lane & 3;
    uint32_t smQ = (uint32_t)__cvta_generic_to_shared(qs);
    uint32_t smK = (uint32_t)__cvta_generic_to_shared(ks);
    uint32_t a_base = smQ + ((uint32_t)(wm0 + (lane & 15)) * ATT_STRIDE + ((lane & 16) ? 4 : 0)) * 4;
    uint32_t b_base = smK + ((uint32_t)(wn0 + (lane & 7) + ((lane & 16) ? 8 : 0)) * ATT_STRIDE
                             + ((lane & 8) ? 4 : 0)) * 4;

    float acc[4][8][4] = {};
    #pragma unroll
    for (int c = 0; c < 4; c++) {
        uint32_t koff = (uint32_t)c * 32;
        uint32_t Bf[8][2];
        #pragma unroll
        for (int t = 0; t < 4; t++)
            ldsm4(Bf[2 * t][0], Bf[2 * t][1], Bf[2 * t + 1][0], Bf[2 * t + 1][1],
                  b_base + koff + (uint32_t)t * 16 * ATT_STRIDE * 4);
        #pragma unroll
        for (int mi = 0; mi < 4; mi++) {
            uint32_t Af[4];
            ldsm4(Af[0], Af[1], Af[2], Af[3],
                  a_base + koff + (uint32_t)mi * 16 * ATT_STRIDE * 4);
            #pragma unroll
            for (int ni = 0; ni < 8; ni++)
                MMA_F16(acc[mi][ni], Af[0], Af[1], Af[2], Af[3], Bf[ni][0], Bf[ni][1]);
        }
    }
    __syncthreads();

    #pragma unroll
    for (int mi = 0; mi < 4; mi++) {
        #pragma unroll
        for (int rr = 0; rr < 2; rr++) {
            int lrow = wm0 + mi * 16 + g + rr * 8;
            int lglob = l0 + lrow;
            const float* qrl = qrb + (size_t)lglob * 512 + (255 - lglob);
            #pragma unroll
            for (int ni = 0; ni < 8; ni++) {
                int m = wn0 + ni * 8 + tg * 2;
                float b0 = qrl[m], b1 = qrl[m + 1];
                acc[mi][ni][rr * 2]     = acc[mi][ni][rr * 2]     * 0.125f + b0 + ((m     > lglob) ? 1.f : 0.f);
                acc[mi][ni][rr * 2 + 1] = acc[mi][ni][rr * 2 + 1] * 0.125f + b1 + ((m + 1 > lglob) ? 1.f : 0.f);
            }
        }
    }

    float rmax[4][2];
    #pragma unroll
    for (int mi = 0; mi < 4; mi++)
        #pragma unroll
        for (int rr = 0; rr < 2; rr++) {
            float mx = -3.4e38f;
            #pragma unroll
            for (int ni = 0; ni < 8; ni++) {
                mx = fmaxf(mx, acc[mi][ni][rr * 2]);
                mx = fmaxf(mx, acc[mi][ni][rr * 2 + 1]);
            }
            mx = fmaxf(mx, __shfl_xor_sync(0xffffffffu, mx, 1));
            mx = fmaxf(mx, __shfl_xor_sync(0xffffffffu, mx, 2));
            int lrow = wm0 + mi * 16 + g + rr * 8;
            if (tg == 0) red[lrow * 4 + warpN] = mx;
            rmax[mi][rr] = 0.f;
        }
    __syncthreads();
    #pragma unroll
    for (int mi = 0; mi < 4; mi++)
        #pragma unroll
        for (int rr = 0; rr < 2; rr++) {
            int lrow = wm0 + mi * 16 + g + rr * 8;
            rmax[mi][rr] = fmaxf(fmaxf(red[lrow * 4 + 0], red[lrow * 4 + 1]),
                                 fmaxf(red[lrow * 4 + 2], red[lrow * 4 + 3]));
        }
    __syncthreads();

    float rsum[4][2];
    #pragma unroll
    for (int mi = 0; mi < 4; mi++)
        #pragma unroll
        for (int rr = 0; rr < 2; rr++) {
            float s = 0.f;
            #pragma unroll
            for (int ni = 0; ni < 8; ni++) {
                float e0 = expf(acc[mi][ni][rr * 2]     - rmax[mi][rr]);
                float e1 = expf(acc[mi][ni][rr * 2 + 1] - rmax[mi][rr]);
                acc[mi][ni][rr * 2] = e0; acc[mi][ni][rr * 2 + 1] = e1;
                s += e0 + e1;
            }
            s += __shfl_xor_sync(0xffffffffu, s, 1);
            s += __shfl_xor_sync(0xffffffffu, s, 2);
            int lrow = wm0 + mi * 16 + g + rr * 8;
            if (tg == 0) red[lrow * 4 + warpN] = s;
            rsum[mi][rr] = 0.f;
        }
    __syncthreads();
    #pragma unroll
    for (int mi = 0; mi < 4; mi++)
        #pragma unroll
        for (int rr = 0; rr < 2; rr++) {
            int lrow = wm0 + mi * 16 + g + rr * 8;
            rsum[mi][rr] = red[lrow * 4 + 0] + red[lrow * 4 + 1]
                         + red[lrow * 4 + 2] + red[lrow * 4 + 3];
        }

    uint32_t* pb = ph + (size_t)bh * (S_LEN * 128);
    #pragma unroll
    for (int mi = 0; mi < 4; mi++)
        #pragma unroll
        for (int rr = 0; rr < 2; rr++) {
            int lglob = l0 + wm0 + mi * 16 + g + rr * 8;
            float inv = 1.f / rsum[mi][rr];
            #pragma unroll
            for (int ni = 0; ni < 8; ni++) {
                float p0 = acc[mi][ni][rr * 2] * inv;
                float p1 = acc[mi][ni][rr * 2 + 1] * inv;
                pb[(size_t)lglob * 128 + (wn0 >> 1) + ni * 4 + tg] = pack_hi(p0, p1);
            }
        }
}

// ---------------- V transpose: qkv hi plane -> vT[bh][64 d][128 s-words] ----------------
__global__ void vtrans_k(const uint32_t* __restrict__ qkvH, uint32_t* __restrict__ vT) {
    __shared__ uint32_t vs[256][33];
    int bh = blockIdx.x;
    int zb = bh >> 3, zh = bh & 7;
    const uint32_t* V = qkvH + (size_t)zb * (256 * 768) + 512 + zh * 32;
    int tid = threadIdx.x;
    #pragma unroll
    for (int j = 0; j < 32; j++) {
        int idx = tid + j * 256;
        int row = idx >> 5, w = idx & 31;
        vs[row][w] = V[(size_t)row * 768 + w];
    }
    __syncthreads();
    uint32_t* o = vT + (size_t)bh * 8192;
    #pragma unroll
    for (int j = 0; j < 32; j++) {
        int idx = tid + j * 256;
        int d = idx >> 7, sw = idx & 127;
        uint32_t w0 = vs[2 * sw][d >> 1], w1 = vs[2 * sw + 1][d >> 1];
        int sh = (d & 1) * 16;
        o[idx] = ((w0 >> sh) & 0xffffu) | (((w1 >> sh) & 0xffffu) << 16);
    }
}

#define STAGES 3

// ---------------- fp16 GEMM, MT x 128 CTA tile, chunk k=16 (8 words) ----------------
// MT = 64 (warp 32x32) or 128 (warp 64x32). ALO: A hi+lo (2-term) vs hi only.
// EPI: 0 = f32 out (+bias); 1 = f32 splitK atomicAdd (+bias at sk==0);
//      2 = planes out bias+GELU; 3 = planes out (+bias, Cl optional).
template<int EPI, int NSPLIT, int ALO, int MT>
__global__ __launch_bounds__(256, 2)
void bgemm(const uint32_t* __restrict__ Ah, const uint32_t* __restrict__ Al,
           const uint32_t* __restrict__ Bh,
           const float* __restrict__ bias,
           float* __restrict__ Cf, uint32_t* __restrict__ Ch, uint32_t* __restrict__ Cl,
           int M, int N, int Kw, int ldaw, int ldbw, int ldc,
           int aOffB, int aOffH, int bOffB, int bOffH, int cOffB, int cOffH) {
    extern __shared__ uint32_t smu[];
    constexpr int APW   = MT * 12;            // A plane words
    constexpr int BPW   = 128 * 12;           // B plane words
    constexpr int BOFFW = (1 + ALO) * APW;
    constexpr int STW   = BOFFW + BPW;
    constexpr int STB   = STW * 4;
    constexpr int WM    = MT / 2;             // warp-row extent
    constexpr int NMI   = MT / 32;            // m16 tiles per warp

    int z = blockIdx.z;
    int sk = z % NSPLIT;
    int zz = z / NSPLIT;
    int zb = zz >> 3, zh = zz & 7;
    Ah += (size_t)zb * aOffB + (size_t)zh * aOffH;
    if (ALO) Al += (size_t)zb * aOffB + (size_t)zh * aOffH;
    Bh += (size_t)zb * bOffB + (size_t)zh * bOffH;
    size_t cAdj = (size_t)zb * cOffB + (size_t)zh * cOffH;
    if (EPI <= 1) Cf += cAdj; else { Ch += cAdj; if (Cl) Cl += cAdj; }

    int kLenW = Kw / NSPLIT;
    int kw0   = sk * kLenW;
    int nk    = kLenW >> 3;

    int tid  = threadIdx.x;
    int lane = tid & 31, wid = tid >> 5;
    int wm0 = (wid >> 2) * WM;
    int wn0 = (wid & 3) * 32;
    int g   = lane >> 2;
    int tg  = lane & 3;
    int row0 = blockIdx.y * MT, col0 = blockIdx.x * 128;

    uint32_t smBase = (uint32_t)__cvta_generic_to_shared(smu);
    uint32_t a_off = ((uint32_t)(wm0 + (lane & 15)) * 12 + ((lane & 16) ? 4 : 0)) * 4;
    uint32_t b_off = ((uint32_t)(wn0 + (lane & 7) + ((lane & 16) ? 8 : 0)) * 12
                      + ((lane & 8) ? 4 : 0)) * 4;

    float acc[NMI][4][4] = {};

    auto COMPUTE = [&](int buf) {
        uint32_t sb = smBase + (uint32_t)buf * STB;
        uint32_t aH = sb + a_off;
        uint32_t aL = aH + APW * 4;
        uint32_t bH = sb + BOFFW * 4 + b_off;
        uint32_t Bhf[4][2];
        ldsm4(Bhf[0][0], Bhf[0][1], Bhf[1][0], Bhf[1][1], bH);
        ldsm4(Bhf[2][0], Bhf[2][1], Bhf[3][0], Bhf[3][1], bH + 16 * 12 * 4);
        #pragma unroll
        for (int mi = 0; mi < NMI; mi++) {
            uint32_t Af[4];
            ldsm4(Af[0], Af[1], Af[2], Af[3], aH + (uint32_t)mi * 16 * 12 * 4);
            uint32_t Lf[4];
            if (ALO) ldsm4(Lf[0], Lf[1], Lf[2], Lf[3], aL + (uint32_t)mi * 16 * 12 * 4);
            #pragma unroll
            for (int ni = 0; ni < 4; ni++) {
                MMA_F16(acc[mi][ni], Af[0], Af[1], Af[2], Af[3], Bhf[ni][0], Bhf[ni][1]);
                if (ALO)
                    MMA_F16(acc[mi][ni], Lf[0], Lf[1], Lf[2], Lf[3], Bhf[ni][0], Bhf[ni][1]);
            }
        }
    };

    auto LOADNT = [&](int chunk, int buf) {
        int kws = kw0 + (chunk << 3);
        uint32_t* st = smu + buf * STW;
        if (MT == 128) {
            int r = tid >> 1, s = (tid & 1) * 4;
            cp16w(st + r * 12 + s, Ah + (size_t)(row0 + r) * ldaw + kws + s, true);
            if (ALO)
                cp16w(st + APW + r * 12 + s, Al + (size_t)(row0 + r) * ldaw + kws + s, true);
        } else {
            int r = (tid & 127) >> 1, s = (tid & 1) * 4;
            if (!ALO) {
                if (tid < 128)
                    cp16w(st + r * 12 + s, Ah + (size_t)(row0 + r) * ldaw + kws + s, true);
            } else {
                const uint32_t* srcp = (tid < 128) ? Ah : Al;
                uint32_t* dstp = st + ((tid < 128) ? 0 : APW);
                cp16w(dstp + r * 12 + s, srcp + (size_t)(row0 + r) * ldaw + kws + s, true);
            }
        }
        int rb = tid >> 1, sb2 = (tid & 1) * 4;
        bool p = (col0 + rb) < N;
        cp16w(st + BOFFW + rb * 12 + sb2, Bh + (size_t)(col0 + rb) * ldbw + kws + sb2, p);
    };

    int pre = (nk < STAGES - 1) ? nk : (STAGES - 1);
    for (int s = 0; s < pre; s++) {
        LOADNT(s, s);
        asm volatile("cp.async.commit_group;");
    }
    for (int i = 0; i < nk; i++) {
        int buf = i % STAGES;
        asm volatile("cp.async.wait_group %0;" :: "n"(STAGES - 2));
        __syncthreads();
        COMPUTE(buf);
        int nxt = i + STAGES - 1;
        if (nxt < nk) LOADNT(nxt, nxt % STAGES);
        asm volatile("cp.async.commit_group;");
    }

    // ---------------- epilogue ----------------
    #pragma unroll
    for (int mi = 0; mi < NMI; mi++) {
        #pragma unroll
        for (int rr = 0; rr < 2; rr++) {
            int r = row0 + wm0 + mi * 16 + g + rr * 8;
            #pragma unroll
            for (int ni = 0; ni < 4; ni++) {
                int c = col0 + wn0 + ni * 8 + tg * 2;
                float v0 = acc[mi][ni][rr * 2];
                float v1 = acc[mi][ni][rr * 2 + 1];
                if (EPI == 0 && NSPLIT == 1) {
                    float* Crow = Cf + (size_t)r * ldc;
                    if (c + 1 < N) {
                        if (bias) { v0 += bias[c]; v1 += bias[c + 1]; }
                        *(float2*)&Crow[c] = make_float2(v0, v1);
                    } else if (c < N) {
                        if (bias) v0 += bias[c];
                        Crow[c] = v0;
                    }
                } else if (EPI == 1) {
                    float* Crow = Cf + (size_t)r * ldc;
                    if (bias && sk == 0) {
                        if (c < N)     v0 += bias[c];
                        if (c + 1 < N) v1 += bias[c + 1];
                    }
                    if (c < N)     atomicAdd(&Crow[c], v0);
                    if (c + 1 < N) atomicAdd(&Crow[c + 1], v1);
                } else if (EPI >= 2) {
                    if (c < N) {
                        if (bias) { v0 += bias[c]; v1 += bias[c + 1]; }
                        if (EPI == 2) {
                            v0 = 0.5f * v0 * (1.f + erff(v0 * 0.7071067811865476f));
                            v1 = 0.5f * v1 * (1.f + erff(v1 * 0.7071067811865476f));
                        }
                        uint32_t h, l;
                        splitpack(v0, v1, h, l);
                        size_t idx = (size_t)r * ldc + (c >> 1);
                        Ch[idx] = h;
                        if (Cl) Cl[idx] = l;
                    }
                }
            }
        }
    }
}

// smem sizes per instantiation
#define SMEM_64_2T  (STAGES * (3 * 64 * 12 + 0 + 128 * 12) * 4)   // (2*APW+BPW)  -> compute below
#define SM_B(MT, ALO) (STAGES * (((1 + (ALO)) * (MT) * 12) + 128 * 12) * 4)

// ---------------- driver ----------------
extern "C" void kernel_launch(void* const* d_in, const int* in_sizes, int n_in,
                              void* d_out, int out_size) {
    const int*   src   = (const int*)  d_in[0];
    const float* emb   = (const float*)d_in[1];
    const float* rel   = (const float*)d_in[2];
    const float* nin_s = (const float*)d_in[3];
    const float* nin_b = (const float*)d_in[4];
    const float* inW   = (const float*)d_in[5];
    const float* inB   = (const float*)d_in[6];
    const float* outW  = (const float*)d_in[7];
    const float* outB  = (const float*)d_in[8];
    const float* ln1s  = (const float*)d_in[9];
    const float* ln1b  = (const float*)d_in[10];
    const float* ln2s  = (const float*)d_in[11];
    const float* ln2b  = (const float*)d_in[12];
    const float* w1    = (const float*)d_in[13];
    const float* b1    = (const float*)d_in[14];
    const float* w2    = (const float*)d_in[15];
    const float* b2    = (const float*)d_in[16];
    const float* nfs   = (const float*)d_in[17];
    const float* nfb   = (const float*)d_in[18];
    const float* decW  = (const float*)d_in[19];
    const float* decB  = (const float*)d_in[20];
    float* out = (float*)d_out;

    float *x, *qr;
    cudaGetSymbolAddress((void**)&x,  g_x);
    cudaGetSymbolAddress((void**)&qr, g_qr);
    uint32_t *hH,*hL,*qkvH,*prH,*vT,*oH,*oL,*gH,*gL;
    uint32_t *WiH,*WoH,*W1H,*W2H,*WdH,*relH;
    cudaGetSymbolAddress((void**)&hH,   p_h_hi);   cudaGetSymbolAddress((void**)&hL,   p_h_lo);
    cudaGetSymbolAddress((void**)&qkvH, p_qkv_hi);
    cudaGetSymbolAddress((void**)&prH,  p_pr_hi);
    cudaGetSymbolAddress((void**)&vT,   p_vT);
    cudaGetSymbolAddress((void**)&oH,   p_o_hi);   cudaGetSymbolAddress((void**)&oL,   p_o_lo);
    cudaGetSymbolAddress((void**)&gH,   p_g_hi);   cudaGetSymbolAddress((void**)&gL,   p_g_lo);
    cudaGetSymbolAddress((void**)&WiH,  p_Wi_hi);
    cudaGetSymbolAddress((void**)&WoH,  p_Wo_hi);
    cudaGetSymbolAddress((void**)&W1H,  p_W1_hi);
    cudaGetSymbolAddress((void**)&W2H,  p_W2_hi);
    cudaGetSymbolAddress((void**)&WdH,  p_Wd_hi);
    cudaGetSymbolAddress((void**)&relH, p_rel_hi);

    cudaFuncSetAttribute(bgemm<3,1,1,64>,  cudaFuncAttributeMaxDynamicSharedMemorySize, SM_B(64,1));
    cudaFuncSetAttribute(bgemm<0,1,0,128>, cudaFuncAttributeMaxDynamicSharedMemorySize, SM_B(128,0));
    cudaFuncSetAttribute(bgemm<3,1,0,64>,  cudaFuncAttributeMaxDynamicSharedMemorySize, SM_B(64,0));
    cudaFuncSetAttribute(bgemm<1,2,1,64>,  cudaFuncAttributeMaxDynamicSharedMemorySize, SM_B(64,1));
    cudaFuncSetAttribute(bgemm<2,1,1,64>,  cudaFuncAttributeMaxDynamicSharedMemorySize, SM_B(64,1));
    cudaFuncSetAttribute(attn_k,           cudaFuncAttributeMaxDynamicSharedMemorySize, ATT_SMEM);

    // weight splits (hi-only)
    split_hi_k<<<(4*1536*256/8 + 255)/256, 256>>>(inW,  WiH, 4*1536*256);
    split_hi_k<<<(4*512*256/8  + 255)/256, 256>>>(outW, WoH, 4*512*256);
    split_hi_k<<<(4*2048*256/8 + 255)/256, 256>>>(w1,   W1H, 4*2048*256);
    split_hi_k<<<(4*512*1024/8 + 255)/256, 256>>>(w2,   W2H, 4*512*1024);
    split_hi_k<<<(V_DIM*256/8  + 255)/256, 256>>>(decW, WdH, V_DIM*256);
    split_hi_k<<<(511*256/8    + 255)/256, 256>>>(rel,  relH, 511*256);

    embed_ln_k<<<N_ROWS, 256>>>(src, emb, nin_s, nin_b, x);

    for (int l = 0; l < 4; l++) {
        const uint32_t* WiHl = WiH + (size_t)l * 1536 * 256;
        const uint32_t* WoHl = WoH + (size_t)l * 512 * 256;
        const uint32_t* W1Hl = W1H + (size_t)l * 2048 * 256;
        const uint32_t* W2Hl = W2H + (size_t)l * 512 * 1024;
        const float* inB_l  = inB  + (size_t)l * QKV_DIM;
        const float* outB_l = outB + (size_t)l * E_DIM;
        const float* b1_l   = b1   + (size_t)l * FF_DIM;
        const float* b2_l   = b2   + (size_t)l * E_DIM;

        layernorm_split_k<<<N_ROWS, 256>>>(x, ln1s + l*E_DIM, ln1b + l*E_DIM, hH, hL);

        // qkv hi plane = h @ inW^T + inB   (2-term A, 64x128 tiles)
        bgemm<3,1,1,64><<<dim3(12, 16, 1), 256, SM_B(64,1)>>>(hH, hL, WiHl, inB_l,
            (float*)0, qkvH, (uint32_t*)0, N_ROWS, QKV_DIM, 256, 256, 256, 768,
            0,0, 0,0, 0,0);

        // V transpose
        vtrans_k<<<N_BH, 256>>>(qkvH, vT);

        // qr f32 = Q @ rel^T  (1-term, 128x128 tiles)
        bgemm<0,1,0,128><<<dim3(4, 2, N_BH), 256, SM_B(128,0)>>>(qkvH, (const uint32_t*)0, relH,
            (const float*)0, qr, (uint32_t*)0, (uint32_t*)0,
            S_LEN, 511, 32, 768, 256, 512,
            256*768, 32, 0, 32, 8*131072, 131072);

        // fused scores + bias + mask + softmax
        attn_k<<<dim3(2, N_BH), 256, ATT_SMEM>>>(qkvH, qr, prH);

        // o planes = probs @ V^T  (1-term, 64x128 tiles)
        bgemm<3,1,0,64><<<dim3(1, 4, N_BH), 256, SM_B(64,0)>>>(prH, (const uint32_t*)0, vT,
            (const float*)0, (float*)0, oH, oL,
            S_LEN, 64, 128, 128, 128, 256,
            8*32768, 32768, 8*8192, 8192, 65536, 32);

        // x += o @ outW^T + outB   (splitK 2, 2-term A, 64x128 tiles)
        bgemm<1,2,1,64><<<dim3(4, 16, 2), 256, SM_B(64,1)>>>(oH, oL, WoHl, outB_l,
            x, (uint32_t*)0, (uint32_t*)0, N_ROWS, E_DIM, 256, 256, 256, E_DIM,
            0,0, 0,0, 0,0);

        layernorm_split_k<<<N_ROWS, 256>>>(x, ln2s + l*E_DIM, ln2b + l*E_DIM, hH, hL);

        // g planes = gelu(h @ w1^T + b1)  (2-term A, 64x128 tiles)
        bgemm<2,1,1,64><<<dim3(16, 16, 1), 256, SM_B(64,1)>>>(hH, hL, W1Hl, b1_l,
            (float*)0, gH, gL, N_ROWS, FF_DIM, 256, 256, 256, 1024,
            0,0, 0,0, 0,0);

        // x += g @ w2^T + b2   (splitK 2, 2-term A, 64x128 tiles)
        bgemm<1,2,1,64><<<dim3(4, 16, 2), 256, SM_B(64,1)>>>(gH, gL, W2Hl, b2_l,
            x, (uint32_t*)0, (uint32_t*)0, N_ROWS, E_DIM, 1024, 1024, 1024, E_DIM,
            0,0, 0,0, 0,0);
    }

    layernorm_split_k<<<N_ROWS, 256>>>(x, nfs, nfb, hH, hL);

    // out f32 = h @ dec_w^T + dec_b   (1-term, 128x128 tiles — stays tensor-bound)
    bgemm<0,1,0,128><<<dim3(250, 8, 1), 256, SM_B(128,0)>>>(hH, (const uint32_t*)0, WdH, decB,
        out, (uint32_t*)0, (uint32_t*)0, N_ROWS, V_DIM, 256, 256, 256, V_DIM,
        0,0, 0,0, 0,0);
}